// round 13
// baseline (speedup 1.0000x reference)
#include <cuda_runtime.h>
#include <cuda_bf16.h>
#include <cuda_fp16.h>
#include <math.h>
#include <cstdint>

#define NNODES 200000
#define NEDGES 800000
#define NG     4096
#define DCELL  954
#define F      128
#define BN_EPS 1e-5f
#define NBLK   782          // ceil(NNODES/256)

// ================= mma.sync helpers =============================================
__device__ __forceinline__ uint32_t smem_to_u32(const void* p) {
    uint32_t a;
    asm("{ .reg .u64 t; cvta.to.shared.u64 t, %1; cvt.u32.u64 %0, t; }" : "=r"(a) : "l"(p));
    return a;
}

#define LDSM_X4(r, addr) \
    asm volatile("ldmatrix.sync.aligned.m8n8.x4.shared.b16 {%0,%1,%2,%3}, [%4];" \
        : "=r"((r)[0]), "=r"((r)[1]), "=r"((r)[2]), "=r"((r)[3]) : "r"(addr))

#define MMA16816(c, a0, a1, a2, a3, b0, b1) \
    asm volatile("mma.sync.aligned.m16n8k16.row.col.f32.bf16.bf16.f32 " \
        "{%0,%1,%2,%3}, {%4,%5,%6,%7}, {%8,%9}, {%0,%1,%2,%3};" \
        : "+f"((c)[0]), "+f"((c)[1]), "+f"((c)[2]), "+f"((c)[3]) \
        : "r"(a0), "r"(a1), "r"(a2), "r"(a3), "r"(b0), "r"(b1))

__device__ __forceinline__ void splitpack(float x, float y, uint32_t& hi, uint32_t& lo) {
    __nv_bfloat16 hx = __float2bfloat16(x), hy = __float2bfloat16(y);
    __nv_bfloat162 h2 = __halves2bfloat162(hx, hy);
    hi = *reinterpret_cast<uint32_t*>(&h2);
    __nv_bfloat162 l2 = __halves2bfloat162(__float2bfloat16(x - __bfloat162float(hx)),
                                           __float2bfloat16(y - __bfloat162float(hy)));
    lo = *reinterpret_cast<uint32_t*>(&l2);
}

__device__ __forceinline__ float2 h2f(uint32_t u) {
    __half2 a = *reinterpret_cast<__half2*>(&u);
    return __half22float2(a);
}

// ================= scratch =======================================================
__device__ float g_bufA[(size_t)NNODES * F];    // h1/h2 as fp16 (reused)
__device__ float g_bufB[(size_t)NNODES * F];    // R split: uint2[node*64+c]={hi,lo}
__device__ float g_dinv[NNODES];
__device__ int   g_deg[NNODES];
__device__ int   g_cursor[NNODES];
__device__ int   g_csr_ptr[NNODES + 1];
__device__ int   g_csr_src[NEDGES];
__device__ float g_csr_w[NEDGES];               // precomputed dinv[dst]*dinv[src]
__device__ int   g_blocksums[1024];
__device__ int   g_blockoff[1024];
__device__ float g_cell[(size_t)NG * F];
__device__ float g_sums[3 * 2 * F];
__device__ float g_const[F];
__device__ int   g_maxb[NG * F];
__device__ __nv_bfloat16 g_w1hi[F * F], g_w1lo[F * F], g_w2hi[F * F], g_w2lo[F * F];

// ================= init / degree / CSR ==========================================
__global__ void init_kernel() {
    int i = blockIdx.x * blockDim.x + threadIdx.x;
    if (i < NNODES) { g_deg[i] = 0; g_cursor[i] = 0; }
    if (i < 2 * 2 * F) g_sums[i] = 0.0f;
    for (int j = i; j < NG * F; j += gridDim.x * blockDim.x) g_maxb[j] = 0;
}
__global__ void zero_cell_sums() {
    g_sums[512 + threadIdx.x] = 0.0f;
}
__global__ void deg_kernel(const int* __restrict__ dst) {
    int e = blockIdx.x * blockDim.x + threadIdx.x;
    if (e < NEDGES) atomicAdd(&g_deg[dst[e]], 1);
}
__global__ void scan1_kernel() {
    __shared__ int sh[256];
    int i = blockIdx.x * 256 + threadIdx.x;
    int v = (i < NNODES) ? g_deg[i] : 0;
    if (i < NNODES) g_dinv[i] = rsqrtf((float)v + 1.0f);
    sh[threadIdx.x] = v;
    __syncthreads();
#pragma unroll
    for (int off = 1; off < 256; off <<= 1) {
        int t = (threadIdx.x >= off) ? sh[threadIdx.x - off] : 0;
        __syncthreads();
        sh[threadIdx.x] += t;
        __syncthreads();
    }
    if (i < NNODES) g_csr_ptr[i] = sh[threadIdx.x] - v;
    if (threadIdx.x == 255) g_blocksums[blockIdx.x] = sh[255];
}
__global__ void scan2_kernel() {
    __shared__ int sh[1024];
    int t = threadIdx.x;
    int v = (t < NBLK) ? g_blocksums[t] : 0;
    sh[t] = v;
    __syncthreads();
#pragma unroll
    for (int off = 1; off < 1024; off <<= 1) {
        int u = (t >= off) ? sh[t - off] : 0;
        __syncthreads();
        sh[t] += u;
        __syncthreads();
    }
    if (t < NBLK) g_blockoff[t] = sh[t] - v;
}
__global__ void scan3_kernel() {
    int i = blockIdx.x * blockDim.x + threadIdx.x;
    if (i < NNODES) g_csr_ptr[i] += g_blockoff[i >> 8];
    if (i == 0) g_csr_ptr[NNODES] = NEDGES;
}
// fill edge list AND precomputed norm weight (dinv ready after scan1)
__global__ void fill_kernel(const int* __restrict__ src, const int* __restrict__ dst) {
    int e = blockIdx.x * blockDim.x + threadIdx.x;
    if (e >= NEDGES) return;
    int d = dst[e];
    int s = src[e];
    int pos = g_csr_ptr[d] + atomicAdd(&g_cursor[d], 1);
    g_csr_src[pos] = s;
    g_csr_w[pos]   = g_dinv[d] * g_dinv[s];
}

// ================= weight prep ===================================================
__global__ void wprep1_kernel(const float* __restrict__ W1) {
    int i = blockIdx.x * blockDim.x + threadIdx.x;
    if (i >= F * F) return;
    int k = i >> 7, n = i & 127;
    float v = W1[i];
    __nv_bfloat16 h = __float2bfloat16(v);
    g_w1hi[n * F + k] = h;
    g_w1lo[n * F + k] = __float2bfloat16(v - __bfloat162float(h));
}

// fold BN1 into W2, affine computed inline from raw sums
__global__ void wprep2_kernel(const float* __restrict__ W2, const float* __restrict__ sums,
                              const float* __restrict__ g1, const float* __restrict__ be1) {
    __shared__ float red[128];
    int n = blockIdx.x, k = threadIdx.x;
    const float invM = 1.0f / (float)NNODES;
    float m   = sums[k] * invM;
    float var = sums[F + k] * invM - m * m;
    float sc  = g1[k] * rsqrtf(var + BN_EPS);
    float sh  = be1[k] - sc * m;
    float w   = W2[k * 128 + n];
    float ws  = w * sc;
    __nv_bfloat16 h = __float2bfloat16(ws);
    g_w2hi[n * 128 + k] = h;
    g_w2lo[n * 128 + k] = __float2bfloat16(ws - __bfloat162float(h));
    red[k] = sh * w;
    __syncthreads();
#pragma unroll
    for (int off = 64; off; off >>= 1) {
        if (k < off) red[k] += red[k + off];
        __syncthreads();
    }
    if (k == 0) g_const[n] = red[0];
}

// ================= GEMM-1: h1(fp16) = split3(x fp32) @ W1 (BM=128) ==============
#define AST    136
#define SW_HI  0
#define SW_LO  (128 * AST * 2)
#define MMA_SMEM (2 * 128 * AST * 2)   // 69632

__global__ void __launch_bounds__(256, 2)
gemm_mma(const float* __restrict__ A, int M,
         const __nv_bfloat16* __restrict__ Whi, const __nv_bfloat16* __restrict__ Wlo,
         __half* __restrict__ C)
{
    extern __shared__ char sm[];
    const int tid  = threadIdx.x;
    const int lane = tid & 31;
    const int wid  = tid >> 5;
    const int m0   = blockIdx.x * 128;

    for (int i = tid; i < 2048; i += 256) {
        int n = i >> 4, kg = i & 15;
        *(uint4*)(sm + SW_HI + ((size_t)n * AST + kg * 8) * 2) = *(const uint4*)(Whi + n * 128 + kg * 8);
        *(uint4*)(sm + SW_LO + ((size_t)n * AST + kg * 8) * 2) = *(const uint4*)(Wlo + n * 128 + kg * 8);
    }
    __syncthreads();

    const int wm = (wid & 3) * 32;
    const int wn = (wid >> 2) * 64;
    uint32_t sb  = smem_to_u32(sm);
    uint32_t brw = wn + (lane >> 4) * 8 + (lane & 7);
    uint32_t bHi = sb + SW_HI + ((brw * AST + ((lane >> 3) & 1) * 8) << 1);
    uint32_t bLo = bHi + SW_LO;

    const int r0 = lane >> 2;
    const int c0 = (lane & 3) * 2;
    const int rowA = m0 + wm + r0;
    const bool okA[2][2] = {{rowA < M, rowA + 8 < M}, {rowA + 16 < M, rowA + 24 < M}};

    float c[2][8][4];
#pragma unroll
    for (int f = 0; f < 2; f++)
#pragma unroll
        for (int j = 0; j < 8; j++)
#pragma unroll
            for (int e = 0; e < 4; e++) c[f][j][e] = 0.0f;

    const float2 Z2 = make_float2(0.f, 0.f);
    float2 raw[2][4];
    {
#pragma unroll
        for (int f = 0; f < 2; f++) {
            const float* p0 = A + (size_t)(rowA + f * 16) * 128 + c0;
            raw[f][0] = okA[f][0] ? *(const float2*)p0          : Z2;
            raw[f][1] = okA[f][1] ? *(const float2*)(p0 + 1024) : Z2;
            raw[f][2] = okA[f][0] ? *(const float2*)(p0 + 8)    : Z2;
            raw[f][3] = okA[f][1] ? *(const float2*)(p0 + 1032) : Z2;
        }
    }

    uint32_t ah[2][4], al[2][4];
    auto do_split = [&](float2 (&rw)[2][4]) {
#pragma unroll
        for (int f = 0; f < 2; f++) {
            splitpack(rw[f][0].x, rw[f][0].y, ah[f][0], al[f][0]);
            splitpack(rw[f][1].x, rw[f][1].y, ah[f][1], al[f][1]);
            splitpack(rw[f][2].x, rw[f][2].y, ah[f][2], al[f][2]);
            splitpack(rw[f][3].x, rw[f][3].y, ah[f][3], al[f][3]);
        }
    };
    do_split(raw);

#pragma unroll
    for (int ks = 0; ks < 8; ks++) {
        float2 rn[2][4];
        if (ks < 7) {
            const int kc = (ks + 1) * 16 + c0;
#pragma unroll
            for (int f = 0; f < 2; f++) {
                const float* p0 = A + (size_t)(rowA + f * 16) * 128 + kc;
                rn[f][0] = okA[f][0] ? *(const float2*)p0          : Z2;
                rn[f][1] = okA[f][1] ? *(const float2*)(p0 + 1024) : Z2;
                rn[f][2] = okA[f][0] ? *(const float2*)(p0 + 8)    : Z2;
                rn[f][3] = okA[f][1] ? *(const float2*)(p0 + 1032) : Z2;
            }
        }
#pragma unroll
        for (int p = 0; p < 4; p++) {
            uint32_t bh[4], bl[4];
            LDSM_X4(bh, bHi + ks * 32 + p * 16 * AST * 2);
            LDSM_X4(bl, bLo + ks * 32 + p * 16 * AST * 2);
#pragma unroll
            for (int f = 0; f < 2; f++)
#pragma unroll
                for (int q = 0; q < 2; q++) {
                    int j = p * 2 + q;
                    MMA16816(c[f][j], ah[f][0], ah[f][1], ah[f][2], ah[f][3], bh[q * 2], bh[q * 2 + 1]);
                    MMA16816(c[f][j], al[f][0], al[f][1], al[f][2], al[f][3], bh[q * 2], bh[q * 2 + 1]);
                    MMA16816(c[f][j], ah[f][0], ah[f][1], ah[f][2], ah[f][3], bl[q * 2], bl[q * 2 + 1]);
                }
        }
        if (ks < 7) do_split(rn);
    }

    const int cc = (lane & 3) * 2;
#pragma unroll
    for (int f = 0; f < 2; f++) {
        int row = m0 + wm + f * 16 + r0;
#pragma unroll
        for (int j = 0; j < 8; j++) {
            int col = wn + j * 8 + cc;
            if (row < M)
                *(__half2*)(C + (size_t)row * 128 + col) = __floats2half2_rn(c[f][j][0], c[f][j][1]);
            if (row + 8 < M)
                *(__half2*)(C + (size_t)(row + 8) * 128 + col) = __floats2half2_rn(c[f][j][2], c[f][j][3]);
        }
    }
}

// ================= GEMM-2 lite: h2(fp16) = (Rhi+Rlo) @ W2' + const (BM=128) =====
#define LCONST (2 * 128 * AST * 2)
#define LITE_SMEM (LCONST + 512)

__global__ void __launch_bounds__(256, 2)
gemm_lite(const uint2* __restrict__ Rq, int M,
          const __nv_bfloat16* __restrict__ Whi, const __nv_bfloat16* __restrict__ Wlo,
          const float* __restrict__ cst, __half* __restrict__ C)
{
    extern __shared__ char sm[];
    float* csm = (float*)(sm + LCONST);
    const int tid  = threadIdx.x;
    const int lane = tid & 31;
    const int wid  = tid >> 5;
    const int m0   = blockIdx.x * 128;

    for (int i = tid; i < 2048; i += 256) {
        int n = i >> 4, kg = i & 15;
        *(uint4*)(sm + SW_HI + ((size_t)n * AST + kg * 8) * 2) = *(const uint4*)(Whi + n * 128 + kg * 8);
        *(uint4*)(sm + SW_LO + ((size_t)n * AST + kg * 8) * 2) = *(const uint4*)(Wlo + n * 128 + kg * 8);
    }
    if (tid < 128) csm[tid] = cst[tid];
    __syncthreads();

    const int wm = (wid & 3) * 32;
    const int wn = (wid >> 2) * 64;
    uint32_t sb  = smem_to_u32(sm);
    uint32_t brw = wn + (lane >> 4) * 8 + (lane & 7);
    uint32_t bHi = sb + SW_HI + ((brw * AST + ((lane >> 3) & 1) * 8) << 1);
    uint32_t bLo = bHi + SW_LO;

    const int r0 = lane >> 2;
    const int q0 = lane & 3;
    const int rowA = m0 + wm + r0;
    const bool okA[2][2] = {{rowA < M, rowA + 8 < M}, {rowA + 16 < M, rowA + 24 < M}};

    float c[2][8][4];
#pragma unroll
    for (int f = 0; f < 2; f++)
#pragma unroll
        for (int j = 0; j < 8; j++)
#pragma unroll
            for (int e = 0; e < 4; e++) c[f][j][e] = 0.0f;

    const uint2 ZU = make_uint2(0u, 0u);
    auto loadA = [&](int ks, uint2 (&fr)[2][4]) {
        int cb = ks * 8 + q0;
#pragma unroll
        for (int f = 0; f < 2; f++) {
            const uint2* p = Rq + (size_t)(rowA + f * 16) * 64 + cb;
            fr[f][0] = okA[f][0] ? p[0]   : ZU;
            fr[f][1] = okA[f][1] ? p[512] : ZU;
            fr[f][2] = okA[f][0] ? p[4]   : ZU;
            fr[f][3] = okA[f][1] ? p[516] : ZU;
        }
    };

    uint2 cur[2][4], nxt[2][4];
    loadA(0, cur);

#pragma unroll
    for (int ks = 0; ks < 8; ks++) {
        if (ks < 7) loadA(ks + 1, nxt);
#pragma unroll
        for (int p = 0; p < 4; p++) {
            uint32_t bh[4], bl[4];
            LDSM_X4(bh, bHi + ks * 32 + p * 16 * AST * 2);
            LDSM_X4(bl, bLo + ks * 32 + p * 16 * AST * 2);
#pragma unroll
            for (int f = 0; f < 2; f++)
#pragma unroll
                for (int q = 0; q < 2; q++) {
                    int j = p * 2 + q;
                    MMA16816(c[f][j], cur[f][0].x, cur[f][1].x, cur[f][2].x, cur[f][3].x, bh[q * 2], bh[q * 2 + 1]);
                    MMA16816(c[f][j], cur[f][0].y, cur[f][1].y, cur[f][2].y, cur[f][3].y, bh[q * 2], bh[q * 2 + 1]);
                    MMA16816(c[f][j], cur[f][0].x, cur[f][1].x, cur[f][2].x, cur[f][3].x, bl[q * 2], bl[q * 2 + 1]);
                }
        }
        if (ks < 7) {
#pragma unroll
            for (int f = 0; f < 2; f++)
#pragma unroll
                for (int i = 0; i < 4; i++) cur[f][i] = nxt[f][i];
        }
    }

    const int cc = (lane & 3) * 2;
#pragma unroll
    for (int f = 0; f < 2; f++) {
        int row = m0 + wm + f * 16 + r0;
#pragma unroll
        for (int j = 0; j < 8; j++) {
            int col = wn + j * 8 + cc;
            float k0 = csm[col], k1 = csm[col + 1];
            if (row < M)
                *(__half2*)(C + (size_t)row * 128 + col) = __floats2half2_rn(c[f][j][0] + k0, c[f][j][1] + k1);
            if (row + 8 < M)
                *(__half2*)(C + (size_t)(row + 8) * 128 + col) = __floats2half2_rn(c[f][j][2] + k0, c[f][j][3] + k1);
        }
    }
}

// ================= half-row gathers: warp-pair per node-group =====================
// Each warp owns a 128B HALF of the feature row (2 features/lane). Two warps
// cover one group of 8 consecutive nodes. 512 thr = 16 warps = 8 groups = 64 nodes.
// NNODES % 64 == 0, so no bounds checks.

// gather-1: r = relu(agg + b1) -> write bf16 hi/lo split (uint2 per feature pair)
__global__ void __launch_bounds__(512)
gather_split_kernel(const __half* __restrict__ h, uint2* __restrict__ Rq2,
                    const float* __restrict__ bias, float* __restrict__ sums)
{
    __shared__ float ss[256];
    int tid = threadIdx.x;
    if (tid < 256) ss[tid] = 0.0f;
    __syncthreads();

    const int lane = tid & 31;
    const int w    = tid >> 5;
    const int half = w & 1;
    const int base = blockIdx.x * 64 + (w >> 1) * 8;
    const int off  = half * 32 + lane;        // uint32 column within row [0,64)
    const int d    = off * 2;                 // feature index
    const float2 b2 = *(const float2*)(bias + d);
    const uint32_t* hw = (const uint32_t*)h;

    float s0 = 0, s1 = 0, q0 = 0, q1 = 0;
#pragma unroll
    for (int i = 0; i < 8; i++) {
        int node = base + i;
        int beg = __ldg(&g_csr_ptr[node]);
        int end = __ldg(&g_csr_ptr[node + 1]);
        float di = __ldg(&g_dinv[node]);
        float2 acc = h2f(hw[(size_t)node * 64 + off]);
        float sn = di * di;
        acc.x *= sn; acc.y *= sn;
        int e = beg;
        for (; e + 3 < end; e += 4) {
            int sa = __ldg(&g_csr_src[e]);
            int sb = __ldg(&g_csr_src[e + 1]);
            int sc = __ldg(&g_csr_src[e + 2]);
            int sd = __ldg(&g_csr_src[e + 3]);
            float na = __ldg(&g_csr_w[e]);
            float nb = __ldg(&g_csr_w[e + 1]);
            float nc = __ldg(&g_csr_w[e + 2]);
            float nd = __ldg(&g_csr_w[e + 3]);
            float2 va = h2f(hw[(size_t)sa * 64 + off]);
            float2 vb = h2f(hw[(size_t)sb * 64 + off]);
            float2 vc = h2f(hw[(size_t)sc * 64 + off]);
            float2 vd = h2f(hw[(size_t)sd * 64 + off]);
            acc.x = fmaf(va.x, na, acc.x); acc.y = fmaf(va.y, na, acc.y);
            acc.x = fmaf(vb.x, nb, acc.x); acc.y = fmaf(vb.y, nb, acc.y);
            acc.x = fmaf(vc.x, nc, acc.x); acc.y = fmaf(vc.y, nc, acc.y);
            acc.x = fmaf(vd.x, nd, acc.x); acc.y = fmaf(vd.y, nd, acc.y);
        }
        for (; e < end; e++) {
            int sa = __ldg(&g_csr_src[e]);
            float na = __ldg(&g_csr_w[e]);
            float2 va = h2f(hw[(size_t)sa * 64 + off]);
            acc.x = fmaf(va.x, na, acc.x); acc.y = fmaf(va.y, na, acc.y);
        }
        float v0 = fmaxf(acc.x + b2.x, 0.0f);
        float v1 = fmaxf(acc.y + b2.y, 0.0f);
        uint32_t hi, lo;
        splitpack(v0, v1, hi, lo);
        Rq2[(size_t)node * 64 + off] = make_uint2(hi, lo);
        s0 += v0; q0 += v0 * v0;
        s1 += v1; q1 += v1 * v1;
    }
    atomicAdd(&ss[d],       s0);  atomicAdd(&ss[128 + d],     q0);
    atomicAdd(&ss[d + 1],   s1);  atomicAdd(&ss[128 + d + 1], q1);
    __syncthreads();
    if (tid < 256) atomicAdd(&sums[tid], ss[tid]);
}

// gather-2: r = relu(agg + b2); BN stats + register pool-max (flush on transitions)
__global__ void __launch_bounds__(512)
gather_pool_kernel(const __half* __restrict__ h, const int* __restrict__ ibatch,
                   const float* __restrict__ bias, float* __restrict__ sums)
{
    __shared__ float ss[256];
    int tid = threadIdx.x;
    if (tid < 256) ss[tid] = 0.0f;
    __syncthreads();

    const int lane = tid & 31;
    const int w    = tid >> 5;
    const int half = w & 1;
    const int base = blockIdx.x * 64 + (w >> 1) * 8;
    const int off  = half * 32 + lane;
    const int d    = off * 2;
    const float2 b2 = *(const float2*)(bias + d);
    const uint32_t* hw = (const uint32_t*)h;

    // hoist 8 graph ids with one lane-parallel load
    int gvl = (lane < 8) ? __ldg(&ibatch[base + lane]) : 0;

    float s0 = 0, s1 = 0, q0 = 0, q1 = 0;
    float m0 = 0, m1 = 0;
    int cur_g = __shfl_sync(0xffffffffu, gvl, 0);

#pragma unroll
    for (int i = 0; i < 8; i++) {
        int node = base + i;
        int g = __shfl_sync(0xffffffffu, gvl, i);
        if (g != cur_g) {
            int* mb = g_maxb + cur_g * F + d;
            atomicMax(mb + 0, __float_as_int(m0));
            atomicMax(mb + 1, __float_as_int(m1));
            cur_g = g;
            m0 = m1 = 0.0f;   // relu values >= 0
        }
        int beg = __ldg(&g_csr_ptr[node]);
        int end = __ldg(&g_csr_ptr[node + 1]);
        float di = __ldg(&g_dinv[node]);
        float2 acc = h2f(hw[(size_t)node * 64 + off]);
        float sn = di * di;
        acc.x *= sn; acc.y *= sn;
        int e = beg;
        for (; e + 3 < end; e += 4) {
            int sa = __ldg(&g_csr_src[e]);
            int sb = __ldg(&g_csr_src[e + 1]);
            int sc = __ldg(&g_csr_src[e + 2]);
            int sd = __ldg(&g_csr_src[e + 3]);
            float na = __ldg(&g_csr_w[e]);
            float nb = __ldg(&g_csr_w[e + 1]);
            float nc = __ldg(&g_csr_w[e + 2]);
            float nd = __ldg(&g_csr_w[e + 3]);
            float2 va = h2f(hw[(size_t)sa * 64 + off]);
            float2 vb = h2f(hw[(size_t)sb * 64 + off]);
            float2 vc = h2f(hw[(size_t)sc * 64 + off]);
            float2 vd = h2f(hw[(size_t)sd * 64 + off]);
            acc.x = fmaf(va.x, na, acc.x); acc.y = fmaf(va.y, na, acc.y);
            acc.x = fmaf(vb.x, nb, acc.x); acc.y = fmaf(vb.y, nb, acc.y);
            acc.x = fmaf(vc.x, nc, acc.x); acc.y = fmaf(vc.y, nc, acc.y);
            acc.x = fmaf(vd.x, nd, acc.x); acc.y = fmaf(vd.y, nd, acc.y);
        }
        for (; e < end; e++) {
            int sa = __ldg(&g_csr_src[e]);
            float na = __ldg(&g_csr_w[e]);
            float2 va = h2f(hw[(size_t)sa * 64 + off]);
            acc.x = fmaf(va.x, na, acc.x); acc.y = fmaf(va.y, na, acc.y);
        }
        float v0 = fmaxf(acc.x + b2.x, 0.0f);
        float v1 = fmaxf(acc.y + b2.y, 0.0f);
        m0 = fmaxf(m0, v0); m1 = fmaxf(m1, v1);
        s0 += v0; q0 += v0 * v0;
        s1 += v1; q1 += v1 * v1;
    }
    {
        int* mb = g_maxb + cur_g * F + d;
        atomicMax(mb + 0, __float_as_int(m0));
        atomicMax(mb + 1, __float_as_int(m1));
    }
    atomicAdd(&ss[d],       s0);  atomicAdd(&ss[128 + d],     q0);
    atomicAdd(&ss[d + 1],   s1);  atomicAdd(&ss[128 + d + 1], q1);
    __syncthreads();
    if (tid < 256) atomicAdd(&sums[tid], ss[tid]);
}

// out = BN2(max) with affine computed inline from raw sums
__global__ void pool_out_kernel(const float* __restrict__ sums2, const float* __restrict__ g2,
                                const float* __restrict__ be2, float* __restrict__ out)
{
    int idx = blockIdx.x * blockDim.x + threadIdx.x;
    if (idx >= NG * F) return;
    int d = idx & 127;
    const float invM = 1.0f / (float)NNODES;
    float m   = sums2[d] * invM;
    float var = sums2[F + d] * invM - m * m;
    float sc  = g2[d] * rsqrtf(var + BN_EPS);
    float v   = __int_as_float(g_maxb[idx]);
    out[idx]  = fmaf(sc, v, be2[d] - sc * m);
}

// ================= cell branch helpers ==========================================
__global__ void bn_stats_kernel(const float* __restrict__ in, float* __restrict__ sums, int M) {
    int d = threadIdx.x;
    float s = 0.0f, q = 0.0f;
    for (int r = blockIdx.x; r < M; r += gridDim.x) {
        float v = in[(size_t)r * F + d];
        s += v; q += v * v;
    }
    atomicAdd(&sums[d], s);
    atomicAdd(&sums[F + d], q);
}

__global__ void bn_apply_kernel(const float* __restrict__ in, const float* __restrict__ sums,
                                const float* __restrict__ gamma, const float* __restrict__ beta,
                                float* __restrict__ out, int M)
{
    int i = blockIdx.x * blockDim.x + threadIdx.x;
    if (i >= M * F) return;
    int d = i & 127;
    float invM = 1.0f / (float)M;
    float m   = sums[d] * invM;
    float var = sums[F + d] * invM - m * m;
    out[i] = gamma[d] * (in[i] - m) * rsqrtf(var + BN_EPS) + beta[d];
}

__global__ __launch_bounds__(256) void gemm128(
    const float* __restrict__ A, const float* __restrict__ B,
    const float* __restrict__ bias, float* __restrict__ C,
    int M, int K, int act)
{
    __shared__ float As[16][132];
    __shared__ float Bs[16][128];
    const int tid = threadIdx.x;
    const int m0  = blockIdx.x * 128;
    const int tn  = tid & 15;
    const int tm  = tid >> 4;
    float acc[8][8];
#pragma unroll
    for (int i = 0; i < 8; i++)
#pragma unroll
        for (int j = 0; j < 8; j++) acc[i][j] = 0.0f;
    const int arow = tid >> 4, acol = tid & 15;
    const int brow = tid >> 7, bcol = tid & 127;
    for (int kk = 0; kk < K; kk += 16) {
#pragma unroll
        for (int p = 0; p < 8; p++) {
            int m = p * 16 + arow, gk = kk + acol, gm = m0 + m;
            float v = 0.0f;
            if (gm < M && gk < K) v = A[(size_t)gm * K + gk];
            As[acol][m] = v;
        }
#pragma unroll
        for (int q = 0; q < 8; q++) {
            int k = q * 2 + brow, gk = kk + k;
            Bs[k][bcol] = (gk < K) ? B[(size_t)gk * 128 + bcol] : 0.0f;
        }
        __syncthreads();
#pragma unroll
        for (int k = 0; k < 16; k++) {
            float4 a0 = *(const float4*)&As[k][tm * 8];
            float4 a1 = *(const float4*)&As[k][tm * 8 + 4];
            float4 b0 = *(const float4*)&Bs[k][tn * 8];
            float4 b1 = *(const float4*)&Bs[k][tn * 8 + 4];
            float a[8] = {a0.x, a0.y, a0.z, a0.w, a1.x, a1.y, a1.z, a1.w};
            float b[8] = {b0.x, b0.y, b0.z, b0.w, b1.x, b1.y, b1.z, b1.w};
#pragma unroll
            for (int i = 0; i < 8; i++)
#pragma unroll
                for (int j = 0; j < 8; j++)
                    acc[i][j] = fmaf(a[i], b[j], acc[i][j]);
        }
        __syncthreads();
    }
#pragma unroll
    for (int i = 0; i < 8; i++) {
        int gm = m0 + tm * 8 + i;
        if (gm >= M) continue;
        float o[8];
#pragma unroll
        for (int j = 0; j < 8; j++) {
            float v = acc[i][j] + bias[tn * 8 + j];
            if (act == 1)      v = fmaxf(v, 0.0f);
            else if (act == 2) v = tanhf(v);
            o[j] = v;
        }
        float4* cp = (float4*)&C[(size_t)gm * 128 + tn * 8];
        cp[0] = make_float4(o[0], o[1], o[2], o[3]);
        cp[1] = make_float4(o[4], o[5], o[6], o[7]);
    }
}

// ================= launch ========================================================
extern "C" void kernel_launch(void* const* d_in, const int* in_sizes, int n_in,
                              void* d_out, int out_size)
{
    const float* x      = (const float*)d_in[0];
    const int*   eidx   = (const int*)  d_in[1];
    const int*   ibatch = (const int*)  d_in[2];
    const float* gexpr  = (const float*)d_in[3];
    const float* W1  = (const float*)d_in[4];
    const float* b1  = (const float*)d_in[5];
    const float* g1  = (const float*)d_in[6];
    const float* be1 = (const float*)d_in[7];
    const float* W2  = (const float*)d_in[8];
    const float* b2  = (const float*)d_in[9];
    const float* g2  = (const float*)d_in[10];
    const float* be2 = (const float*)d_in[11];
    const float* Wc1 = (const float*)d_in[12];
    const float* bc1 = (const float*)d_in[13];
    const float* gc  = (const float*)d_in[14];
    const float* bec = (const float*)d_in[15];
    const float* Wc2 = (const float*)d_in[16];
    const float* bc2 = (const float*)d_in[17];
    float* out = (float*)d_out;

    const int* src = eidx;
    const int* dst = eidx + NEDGES;

    float* bufA; cudaGetSymbolAddress((void**)&bufA, g_bufA);
    float* bufB; cudaGetSymbolAddress((void**)&bufB, g_bufB);
    float* cell; cudaGetSymbolAddress((void**)&cell, g_cell);
    float* sums; cudaGetSymbolAddress((void**)&sums, g_sums);
    float* cst;  cudaGetSymbolAddress((void**)&cst,  g_const);
    __nv_bfloat16 *w1hi, *w1lo, *w2hi, *w2lo;
    cudaGetSymbolAddress((void**)&w1hi, g_w1hi);
    cudaGetSymbolAddress((void**)&w1lo, g_w1lo);
    cudaGetSymbolAddress((void**)&w2hi, g_w2hi);
    cudaGetSymbolAddress((void**)&w2lo, g_w2lo);
    __half* hbuf = (__half*)bufA;

    cudaFuncSetAttribute(gemm_mma,  cudaFuncAttributeMaxDynamicSharedMemorySize, MMA_SMEM);
    cudaFuncSetAttribute(gemm_lite, cudaFuncAttributeMaxDynamicSharedMemorySize, LITE_SMEM);

    static cudaStream_t s_csr = nullptr, s_cell = nullptr;
    static cudaEvent_t ev_root = nullptr, ev_csr = nullptr, ev_cell = nullptr;
    if (!s_csr) {
        cudaStreamCreateWithFlags(&s_csr,  cudaStreamNonBlocking);
        cudaStreamCreateWithFlags(&s_cell, cudaStreamNonBlocking);
        cudaEventCreateWithFlags(&ev_root, cudaEventDisableTiming);
        cudaEventCreateWithFlags(&ev_csr,  cudaEventDisableTiming);
        cudaEventCreateWithFlags(&ev_cell, cudaEventDisableTiming);
    }

    const int T = 256;
    int gN  = (NNODES + T - 1) / T;
    int gE  = (NEDGES + T - 1) / T;
    int gGF = (NG * F + T - 1) / T;
    int gGather = NNODES / 64;            // 3125 blocks x 16 warps (warp-pair per 8 nodes)
    int gTile   = (NNODES + 127) / 128;   // 1563
    int gGemmG  = (NG + 127) / 128;

    // ---- fork
    cudaEventRecord(ev_root, 0);
    cudaStreamWaitEvent(s_csr,  ev_root, 0);
    cudaStreamWaitEvent(s_cell, ev_root, 0);

    // submissions 1-4 (gemm_mma stays in ncu slot)
    init_kernel<<<gN, T, 0, s_csr>>>();
    deg_kernel<<<gE, T, 0, s_csr>>>(dst);
    wprep1_kernel<<<(F * F + 255) / 256, 256>>>(W1);
    gemm_mma<<<gTile, 256, MMA_SMEM>>>(x, NNODES, w1hi, w1lo, hbuf);

    // ---- rest of CSR branch
    scan1_kernel<<<NBLK, 256, 0, s_csr>>>();
    scan2_kernel<<<1, 1024, 0, s_csr>>>();
    scan3_kernel<<<gN, T, 0, s_csr>>>();
    fill_kernel<<<gE, T, 0, s_csr>>>(src, dst);
    cudaEventRecord(ev_csr, s_csr);

    // ---- cell branch
    zero_cell_sums<<<1, 256, 0, s_cell>>>();
    gemm128<<<gGemmG, 256, 0, s_cell>>>(gexpr, Wc1, bc1, cell, NG, DCELL, 2);
    bn_stats_kernel<<<512, 128, 0, s_cell>>>(cell, sums + 512, NG);
    bn_apply_kernel<<<gGF, T, 0, s_cell>>>(cell, sums + 512, gc, bec, cell, NG);
    gemm128<<<gGemmG, 256, 0, s_cell>>>(cell, Wc2, bc2, out + (size_t)NG * F, NG, 128, 1);
    cudaEventRecord(ev_cell, s_cell);

    // ---- main: join CSR, aggregation pipeline
    cudaStreamWaitEvent(0, ev_csr, 0);
    gather_split_kernel<<<gGather, 512>>>(hbuf, (uint2*)bufB, b1, sums + 0);
    wprep2_kernel<<<128, 128>>>(W2, sums + 0, g1, be1);

    gemm_lite<<<gTile, 256, LITE_SMEM>>>((const uint2*)bufB, NNODES, w2hi, w2lo, cst, hbuf);
    gather_pool_kernel<<<gGather, 512>>>(hbuf, ibatch, b2, sums + 256);
    pool_out_kernel<<<gGF, T>>>(sums + 256, g2, be2, out);

    // ---- join cell branch
    cudaStreamWaitEvent(0, ev_cell, 0);
}

// round 14
// speedup vs baseline: 1.1424x; 1.1424x over previous
#include <cuda_runtime.h>
#include <cuda_bf16.h>
#include <cuda_fp16.h>
#include <math.h>
#include <cstdint>

#define NNODES 200000
#define NEDGES 800000
#define NG     4096
#define DCELL  954
#define F      128
#define BN_EPS 1e-5f
#define NBLK   782          // ceil(NNODES/256)

// ================= mma.sync helpers =============================================
__device__ __forceinline__ uint32_t smem_to_u32(const void* p) {
    uint32_t a;
    asm("{ .reg .u64 t; cvta.to.shared.u64 t, %1; cvt.u32.u64 %0, t; }" : "=r"(a) : "l"(p));
    return a;
}

#define LDSM_X4(r, addr) \
    asm volatile("ldmatrix.sync.aligned.m8n8.x4.shared.b16 {%0,%1,%2,%3}, [%4];" \
        : "=r"((r)[0]), "=r"((r)[1]), "=r"((r)[2]), "=r"((r)[3]) : "r"(addr))

#define MMA16816(c, a0, a1, a2, a3, b0, b1) \
    asm volatile("mma.sync.aligned.m16n8k16.row.col.f32.bf16.bf16.f32 " \
        "{%0,%1,%2,%3}, {%4,%5,%6,%7}, {%8,%9}, {%0,%1,%2,%3};" \
        : "+f"((c)[0]), "+f"((c)[1]), "+f"((c)[2]), "+f"((c)[3]) \
        : "r"(a0), "r"(a1), "r"(a2), "r"(a3), "r"(b0), "r"(b1))

__device__ __forceinline__ void splitpack(float x, float y, uint32_t& hi, uint32_t& lo) {
    __nv_bfloat16 hx = __float2bfloat16(x), hy = __float2bfloat16(y);
    __nv_bfloat162 h2 = __halves2bfloat162(hx, hy);
    hi = *reinterpret_cast<uint32_t*>(&h2);
    __nv_bfloat162 l2 = __halves2bfloat162(__float2bfloat16(x - __bfloat162float(hx)),
                                           __float2bfloat16(y - __bfloat162float(hy)));
    lo = *reinterpret_cast<uint32_t*>(&l2);
}

__device__ __forceinline__ float4 h4f(uint2 u) {
    __half2 a = *reinterpret_cast<__half2*>(&u.x);
    __half2 b = *reinterpret_cast<__half2*>(&u.y);
    float2 fa = __half22float2(a), fb = __half22float2(b);
    return make_float4(fa.x, fa.y, fb.x, fb.y);
}

// ================= scratch =======================================================
__device__ float g_bufA[(size_t)NNODES * F];    // h1/h2 as fp16 (reused)
__device__ float g_bufB[(size_t)NNODES * F];    // R split: uint2[node*64+c]={hi,lo}
__device__ float g_dinv[NNODES];
__device__ int   g_deg[NNODES];
__device__ int   g_cursor[NNODES];
__device__ int   g_csr_ptr[NNODES + 1];
__device__ int   g_csr_src[NEDGES];
__device__ float g_csr_w[NEDGES];               // precomputed dinv[dst]*dinv[src]
__device__ int   g_blocksums[1024];
__device__ int   g_blockoff[1024];
__device__ float g_cell[(size_t)NG * F];
__device__ float g_sums[3 * 2 * F];
__device__ float g_const[F];
__device__ int   g_maxb[NG * F];
__device__ __nv_bfloat16 g_w1hi[F * F], g_w1lo[F * F], g_w2hi[F * F], g_w2lo[F * F];

// ================= init / degree / CSR ==========================================
__global__ void init_kernel() {
    int i = blockIdx.x * blockDim.x + threadIdx.x;
    if (i < NNODES) { g_deg[i] = 0; g_cursor[i] = 0; }
    if (i < 2 * 2 * F) g_sums[i] = 0.0f;
    for (int j = i; j < NG * F; j += gridDim.x * blockDim.x) g_maxb[j] = 0;
}
__global__ void zero_cell_sums() {
    g_sums[512 + threadIdx.x] = 0.0f;
}
__global__ void deg_kernel(const int* __restrict__ dst) {
    int e = blockIdx.x * blockDim.x + threadIdx.x;
    if (e < NEDGES) atomicAdd(&g_deg[dst[e]], 1);
}
__global__ void scan1_kernel() {
    __shared__ int sh[256];
    int i = blockIdx.x * 256 + threadIdx.x;
    int v = (i < NNODES) ? g_deg[i] : 0;
    if (i < NNODES) g_dinv[i] = rsqrtf((float)v + 1.0f);
    sh[threadIdx.x] = v;
    __syncthreads();
#pragma unroll
    for (int off = 1; off < 256; off <<= 1) {
        int t = (threadIdx.x >= off) ? sh[threadIdx.x - off] : 0;
        __syncthreads();
        sh[threadIdx.x] += t;
        __syncthreads();
    }
    if (i < NNODES) g_csr_ptr[i] = sh[threadIdx.x] - v;
    if (threadIdx.x == 255) g_blocksums[blockIdx.x] = sh[255];
}
__global__ void scan2_kernel() {
    __shared__ int sh[1024];
    int t = threadIdx.x;
    int v = (t < NBLK) ? g_blocksums[t] : 0;
    sh[t] = v;
    __syncthreads();
#pragma unroll
    for (int off = 1; off < 1024; off <<= 1) {
        int u = (t >= off) ? sh[t - off] : 0;
        __syncthreads();
        sh[t] += u;
        __syncthreads();
    }
    if (t < NBLK) g_blockoff[t] = sh[t] - v;
}
__global__ void scan3_kernel() {
    int i = blockIdx.x * blockDim.x + threadIdx.x;
    if (i < NNODES) g_csr_ptr[i] += g_blockoff[i >> 8];
    if (i == 0) g_csr_ptr[NNODES] = NEDGES;
}
// fill edge list AND precomputed norm weight (dinv ready after scan1)
__global__ void fill_kernel(const int* __restrict__ src, const int* __restrict__ dst) {
    int e = blockIdx.x * blockDim.x + threadIdx.x;
    if (e >= NEDGES) return;
    int d = dst[e];
    int s = src[e];
    int pos = g_csr_ptr[d] + atomicAdd(&g_cursor[d], 1);
    g_csr_src[pos] = s;
    g_csr_w[pos]   = g_dinv[d] * g_dinv[s];
}

// ================= weight prep ===================================================
__global__ void wprep1_kernel(const float* __restrict__ W1) {
    int i = blockIdx.x * blockDim.x + threadIdx.x;
    if (i >= F * F) return;
    int k = i >> 7, n = i & 127;
    float v = W1[i];
    __nv_bfloat16 h = __float2bfloat16(v);
    g_w1hi[n * F + k] = h;
    g_w1lo[n * F + k] = __float2bfloat16(v - __bfloat162float(h));
}

// fold BN1 into W2, affine computed inline from raw sums
__global__ void wprep2_kernel(const float* __restrict__ W2, const float* __restrict__ sums,
                              const float* __restrict__ g1, const float* __restrict__ be1) {
    __shared__ float red[128];
    int n = blockIdx.x, k = threadIdx.x;
    const float invM = 1.0f / (float)NNODES;
    float m   = sums[k] * invM;
    float var = sums[F + k] * invM - m * m;
    float sc  = g1[k] * rsqrtf(var + BN_EPS);
    float sh  = be1[k] - sc * m;
    float w   = W2[k * 128 + n];
    float ws  = w * sc;
    __nv_bfloat16 h = __float2bfloat16(ws);
    g_w2hi[n * 128 + k] = h;
    g_w2lo[n * 128 + k] = __float2bfloat16(ws - __bfloat162float(h));
    red[k] = sh * w;
    __syncthreads();
#pragma unroll
    for (int off = 64; off; off >>= 1) {
        if (k < off) red[k] += red[k + off];
        __syncthreads();
    }
    if (k == 0) g_const[n] = red[0];
}

// ================= GEMM-1: h1(fp16) = split3(x fp32) @ W1 (BM=128) ==============
#define AST    136
#define SW_HI  0
#define SW_LO  (128 * AST * 2)
#define MMA_SMEM (2 * 128 * AST * 2)   // 69632

__global__ void __launch_bounds__(256, 2)
gemm_mma(const float* __restrict__ A, int M,
         const __nv_bfloat16* __restrict__ Whi, const __nv_bfloat16* __restrict__ Wlo,
         __half* __restrict__ C)
{
    extern __shared__ char sm[];
    const int tid  = threadIdx.x;
    const int lane = tid & 31;
    const int wid  = tid >> 5;
    const int m0   = blockIdx.x * 128;

    for (int i = tid; i < 2048; i += 256) {
        int n = i >> 4, kg = i & 15;
        *(uint4*)(sm + SW_HI + ((size_t)n * AST + kg * 8) * 2) = *(const uint4*)(Whi + n * 128 + kg * 8);
        *(uint4*)(sm + SW_LO + ((size_t)n * AST + kg * 8) * 2) = *(const uint4*)(Wlo + n * 128 + kg * 8);
    }
    __syncthreads();

    const int wm = (wid & 3) * 32;
    const int wn = (wid >> 2) * 64;
    uint32_t sb  = smem_to_u32(sm);
    uint32_t brw = wn + (lane >> 4) * 8 + (lane & 7);
    uint32_t bHi = sb + SW_HI + ((brw * AST + ((lane >> 3) & 1) * 8) << 1);
    uint32_t bLo = bHi + SW_LO;

    const int r0 = lane >> 2;
    const int c0 = (lane & 3) * 2;
    const int rowA = m0 + wm + r0;
    const bool okA[2][2] = {{rowA < M, rowA + 8 < M}, {rowA + 16 < M, rowA + 24 < M}};

    float c[2][8][4];
#pragma unroll
    for (int f = 0; f < 2; f++)
#pragma unroll
        for (int j = 0; j < 8; j++)
#pragma unroll
            for (int e = 0; e < 4; e++) c[f][j][e] = 0.0f;

    const float2 Z2 = make_float2(0.f, 0.f);
    float2 raw[2][4];
    {
#pragma unroll
        for (int f = 0; f < 2; f++) {
            const float* p0 = A + (size_t)(rowA + f * 16) * 128 + c0;
            raw[f][0] = okA[f][0] ? *(const float2*)p0          : Z2;
            raw[f][1] = okA[f][1] ? *(const float2*)(p0 + 1024) : Z2;
            raw[f][2] = okA[f][0] ? *(const float2*)(p0 + 8)    : Z2;
            raw[f][3] = okA[f][1] ? *(const float2*)(p0 + 1032) : Z2;
        }
    }

    uint32_t ah[2][4], al[2][4];
    auto do_split = [&](float2 (&rw)[2][4]) {
#pragma unroll
        for (int f = 0; f < 2; f++) {
            splitpack(rw[f][0].x, rw[f][0].y, ah[f][0], al[f][0]);
            splitpack(rw[f][1].x, rw[f][1].y, ah[f][1], al[f][1]);
            splitpack(rw[f][2].x, rw[f][2].y, ah[f][2], al[f][2]);
            splitpack(rw[f][3].x, rw[f][3].y, ah[f][3], al[f][3]);
        }
    };
    do_split(raw);

#pragma unroll
    for (int ks = 0; ks < 8; ks++) {
        float2 rn[2][4];
        if (ks < 7) {
            const int kc = (ks + 1) * 16 + c0;
#pragma unroll
            for (int f = 0; f < 2; f++) {
                const float* p0 = A + (size_t)(rowA + f * 16) * 128 + kc;
                rn[f][0] = okA[f][0] ? *(const float2*)p0          : Z2;
                rn[f][1] = okA[f][1] ? *(const float2*)(p0 + 1024) : Z2;
                rn[f][2] = okA[f][0] ? *(const float2*)(p0 + 8)    : Z2;
                rn[f][3] = okA[f][1] ? *(const float2*)(p0 + 1032) : Z2;
            }
        }
#pragma unroll
        for (int p = 0; p < 4; p++) {
            uint32_t bh[4], bl[4];
            LDSM_X4(bh, bHi + ks * 32 + p * 16 * AST * 2);
            LDSM_X4(bl, bLo + ks * 32 + p * 16 * AST * 2);
#pragma unroll
            for (int f = 0; f < 2; f++)
#pragma unroll
                for (int q = 0; q < 2; q++) {
                    int j = p * 2 + q;
                    MMA16816(c[f][j], ah[f][0], ah[f][1], ah[f][2], ah[f][3], bh[q * 2], bh[q * 2 + 1]);
                    MMA16816(c[f][j], al[f][0], al[f][1], al[f][2], al[f][3], bh[q * 2], bh[q * 2 + 1]);
                    MMA16816(c[f][j], ah[f][0], ah[f][1], ah[f][2], ah[f][3], bl[q * 2], bl[q * 2 + 1]);
                }
        }
        if (ks < 7) do_split(rn);
    }

    const int cc = (lane & 3) * 2;
#pragma unroll
    for (int f = 0; f < 2; f++) {
        int row = m0 + wm + f * 16 + r0;
#pragma unroll
        for (int j = 0; j < 8; j++) {
            int col = wn + j * 8 + cc;
            if (row < M)
                *(__half2*)(C + (size_t)row * 128 + col) = __floats2half2_rn(c[f][j][0], c[f][j][1]);
            if (row + 8 < M)
                *(__half2*)(C + (size_t)(row + 8) * 128 + col) = __floats2half2_rn(c[f][j][2], c[f][j][3]);
        }
    }
}

// ================= GEMM-2 lite: N-SPLIT (128 rows x 64 cols per CTA) ============
// blockIdx.x = (mtile << 1) | nhalf. Half W in smem (35KB) -> 3 CTAs/SM.
#define LSW_HI 0
#define LSW_LO (64 * AST * 2)          // 17408
#define LCONST (2 * 64 * AST * 2)      // 34816
#define LITE_SMEM (LCONST + 256)       // + 64 floats const

__global__ void __launch_bounds__(256, 3)
gemm_lite(const uint2* __restrict__ Rq, int M,
          const __nv_bfloat16* __restrict__ Whi, const __nv_bfloat16* __restrict__ Wlo,
          const float* __restrict__ cst, __half* __restrict__ C)
{
    extern __shared__ char sm[];
    float* csm = (float*)(sm + LCONST);
    const int tid  = threadIdx.x;
    const int lane = tid & 31;
    const int wid  = tid >> 5;
    const int m0   = (blockIdx.x >> 1) * 128;
    const int nh   = (blockIdx.x & 1) * 64;     // column half base

    // load this CTA's 64 W rows (hi+lo)
    for (int i = tid; i < 1024; i += 256) {
        int n = i >> 4, kg = i & 15;
        *(uint4*)(sm + LSW_HI + ((size_t)n * AST + kg * 8) * 2) = *(const uint4*)(Whi + (size_t)(nh + n) * 128 + kg * 8);
        *(uint4*)(sm + LSW_LO + ((size_t)n * AST + kg * 8) * 2) = *(const uint4*)(Wlo + (size_t)(nh + n) * 128 + kg * 8);
    }
    if (tid < 64) csm[tid] = cst[nh + tid];
    __syncthreads();

    const int wm = (wid & 3) * 32;
    const int wn = (wid >> 2) * 32;             // 2 N-warps x 32 cols
    uint32_t sb  = smem_to_u32(sm);
    uint32_t brw = wn + (lane >> 4) * 8 + (lane & 7);
    uint32_t bHi = sb + LSW_HI + ((brw * AST + ((lane >> 3) & 1) * 8) << 1);
    uint32_t bLo = bHi + LSW_LO;

    const int r0 = lane >> 2;
    const int q0 = lane & 3;
    const int rowA = m0 + wm + r0;
    const bool okA[2][2] = {{rowA < M, rowA + 8 < M}, {rowA + 16 < M, rowA + 24 < M}};

    float c[2][4][4];
#pragma unroll
    for (int f = 0; f < 2; f++)
#pragma unroll
        for (int j = 0; j < 4; j++)
#pragma unroll
            for (int e = 0; e < 4; e++) c[f][j][e] = 0.0f;

    const uint2 ZU = make_uint2(0u, 0u);
    auto loadA = [&](int ks, uint2 (&fr)[2][4]) {
        int cb = ks * 8 + q0;
#pragma unroll
        for (int f = 0; f < 2; f++) {
            const uint2* p = Rq + (size_t)(rowA + f * 16) * 64 + cb;
            fr[f][0] = okA[f][0] ? p[0]   : ZU;
            fr[f][1] = okA[f][1] ? p[512] : ZU;
            fr[f][2] = okA[f][0] ? p[4]   : ZU;
            fr[f][3] = okA[f][1] ? p[516] : ZU;
        }
    };

    uint2 cur[2][4], nxt[2][4];
    loadA(0, cur);

#pragma unroll
    for (int ks = 0; ks < 8; ks++) {
        if (ks < 7) loadA(ks + 1, nxt);
#pragma unroll
        for (int p = 0; p < 2; p++) {
            uint32_t bh[4], bl[4];
            LDSM_X4(bh, bHi + ks * 32 + p * 16 * AST * 2);
            LDSM_X4(bl, bLo + ks * 32 + p * 16 * AST * 2);
#pragma unroll
            for (int f = 0; f < 2; f++)
#pragma unroll
                for (int q = 0; q < 2; q++) {
                    int j = p * 2 + q;
                    MMA16816(c[f][j], cur[f][0].x, cur[f][1].x, cur[f][2].x, cur[f][3].x, bh[q * 2], bh[q * 2 + 1]);
                    MMA16816(c[f][j], cur[f][0].y, cur[f][1].y, cur[f][2].y, cur[f][3].y, bh[q * 2], bh[q * 2 + 1]);
                    MMA16816(c[f][j], cur[f][0].x, cur[f][1].x, cur[f][2].x, cur[f][3].x, bl[q * 2], bl[q * 2 + 1]);
                }
        }
        if (ks < 7) {
#pragma unroll
            for (int f = 0; f < 2; f++)
#pragma unroll
                for (int i = 0; i < 4; i++) cur[f][i] = nxt[f][i];
        }
    }

    const int cc = (lane & 3) * 2;
#pragma unroll
    for (int f = 0; f < 2; f++) {
        int row = m0 + wm + f * 16 + r0;
#pragma unroll
        for (int j = 0; j < 4; j++) {
            int lcol = wn + j * 8 + cc;
            int col  = nh + lcol;
            float k0 = csm[lcol], k1 = csm[lcol + 1];
            if (row < M)
                *(__half2*)(C + (size_t)row * 128 + col) = __floats2half2_rn(c[f][j][0] + k0, c[f][j][1] + k1);
            if (row + 8 < M)
                *(__half2*)(C + (size_t)(row + 8) * 128 + col) = __floats2half2_rn(c[f][j][2] + k0, c[f][j][3] + k1);
        }
    }
}

// ================= gather core (CSR, fp16 rows, precomputed edge weights) ========
__device__ __forceinline__ float4 gather_acc(const __half* __restrict__ h, int node, int lane) {
    int beg = g_csr_ptr[node];
    int end = g_csr_ptr[node + 1];
    float di = g_dinv[node];
    const uint2* hv = (const uint2*)h;
    float4 acc = h4f(hv[(size_t)node * 32 + lane]);
    float sn = di * di;
    acc.x *= sn; acc.y *= sn; acc.z *= sn; acc.w *= sn;
    int e = beg;
    for (; e + 3 < end; e += 4) {
        int s0 = __ldg(&g_csr_src[e]);
        int s1 = __ldg(&g_csr_src[e + 1]);
        int s2 = __ldg(&g_csr_src[e + 2]);
        int s3 = __ldg(&g_csr_src[e + 3]);
        float n0 = __ldg(&g_csr_w[e]);
        float n1 = __ldg(&g_csr_w[e + 1]);
        float n2 = __ldg(&g_csr_w[e + 2]);
        float n3 = __ldg(&g_csr_w[e + 3]);
        float4 v0 = h4f(hv[(size_t)s0 * 32 + lane]);
        float4 v1 = h4f(hv[(size_t)s1 * 32 + lane]);
        float4 v2 = h4f(hv[(size_t)s2 * 32 + lane]);
        float4 v3 = h4f(hv[(size_t)s3 * 32 + lane]);
        acc.x = fmaf(v0.x, n0, acc.x); acc.y = fmaf(v0.y, n0, acc.y);
        acc.z = fmaf(v0.z, n0, acc.z); acc.w = fmaf(v0.w, n0, acc.w);
        acc.x = fmaf(v1.x, n1, acc.x); acc.y = fmaf(v1.y, n1, acc.y);
        acc.z = fmaf(v1.z, n1, acc.z); acc.w = fmaf(v1.w, n1, acc.w);
        acc.x = fmaf(v2.x, n2, acc.x); acc.y = fmaf(v2.y, n2, acc.y);
        acc.z = fmaf(v2.z, n2, acc.z); acc.w = fmaf(v2.w, n2, acc.w);
        acc.x = fmaf(v3.x, n3, acc.x); acc.y = fmaf(v3.y, n3, acc.y);
        acc.z = fmaf(v3.z, n3, acc.z); acc.w = fmaf(v3.w, n3, acc.w);
    }
    for (; e < end; e++) {
        int s0 = __ldg(&g_csr_src[e]);
        float n0 = __ldg(&g_csr_w[e]);
        float4 v0 = h4f(hv[(size_t)s0 * 32 + lane]);
        acc.x = fmaf(v0.x, n0, acc.x); acc.y = fmaf(v0.y, n0, acc.y);
        acc.z = fmaf(v0.z, n0, acc.z); acc.w = fmaf(v0.w, n0, acc.w);
    }
    return acc;
}

#define NPW 8   // nodes per warp

// gather-1: warp owns 8 consecutive nodes; BN sums in REGISTERS (R12/R10 shape)
__global__ void gather_split_kernel(const __half* __restrict__ h, uint4* __restrict__ Rq4,
                                    const float* __restrict__ bias, float* __restrict__ sums)
{
    __shared__ float ss[256];
    int tid = threadIdx.x;                    // 512 threads = 16 warps = 128 nodes
    if (tid < 256) ss[tid] = 0.0f;
    __syncthreads();

    int lane = tid & 31;
    int base = blockIdx.x * 128 + (tid >> 5) * NPW;
    int d = lane * 4;
    float4 b4 = make_float4(bias[d], bias[d + 1], bias[d + 2], bias[d + 3]);

    float s0 = 0, s1 = 0, s2 = 0, s3 = 0, q0 = 0, q1 = 0, q2 = 0, q3 = 0;
    for (int i = 0; i < NPW; i++) {
        int node = base + i;
        if (node >= NNODES) break;
        float4 acc = gather_acc(h, node, lane);
        float v0 = fmaxf(acc.x + b4.x, 0.0f);
        float v1 = fmaxf(acc.y + b4.y, 0.0f);
        float v2 = fmaxf(acc.z + b4.z, 0.0f);
        float v3 = fmaxf(acc.w + b4.w, 0.0f);
        uint32_t h01, l01, h23, l23;
        splitpack(v0, v1, h01, l01);
        splitpack(v2, v3, h23, l23);
        Rq4[(size_t)node * 32 + lane] = make_uint4(h01, l01, h23, l23);
        s0 += v0; q0 += v0 * v0;
        s1 += v1; q1 += v1 * v1;
        s2 += v2; q2 += v2 * v2;
        s3 += v3; q3 += v3 * v3;
    }
    atomicAdd(&ss[d + 0], s0);  atomicAdd(&ss[128 + d + 0], q0);
    atomicAdd(&ss[d + 1], s1);  atomicAdd(&ss[128 + d + 1], q1);
    atomicAdd(&ss[d + 2], s2);  atomicAdd(&ss[128 + d + 2], q2);
    atomicAdd(&ss[d + 3], s3);  atomicAdd(&ss[128 + d + 3], q3);
    __syncthreads();
    if (tid < 256) atomicAdd(&sums[tid], ss[tid]);
}

// gather-2: register BN sums + register pool-max flushed on graph transitions
__global__ void gather_pool_kernel(const __half* __restrict__ h, const int* __restrict__ ibatch,
                                   const float* __restrict__ bias, float* __restrict__ sums)
{
    __shared__ float ss[256];
    int tid = threadIdx.x;
    if (tid < 256) ss[tid] = 0.0f;
    __syncthreads();

    int lane = tid & 31;
    int base = blockIdx.x * 128 + (tid >> 5) * NPW;
    int d = lane * 4;
    float4 b4 = make_float4(bias[d], bias[d + 1], bias[d + 2], bias[d + 3]);

    float s0 = 0, s1 = 0, s2 = 0, s3 = 0, q0 = 0, q1 = 0, q2 = 0, q3 = 0;
    float m0 = 0, m1 = 0, m2 = 0, m3 = 0;
    int cur_g = -1;

    for (int i = 0; i < NPW; i++) {
        int node = base + i;
        if (node >= NNODES) break;
        int g = 0;
        if (lane == 0) g = __ldg(&ibatch[node]);
        g = __shfl_sync(0xffffffffu, g, 0);
        if (g != cur_g) {
            if (cur_g >= 0) {
                int* mb = g_maxb + cur_g * F + d;
                atomicMax(mb + 0, __float_as_int(m0));
                atomicMax(mb + 1, __float_as_int(m1));
                atomicMax(mb + 2, __float_as_int(m2));
                atomicMax(mb + 3, __float_as_int(m3));
            }
            cur_g = g;
            m0 = m1 = m2 = m3 = 0.0f;   // values are relu >= 0
        }
        float4 acc = gather_acc(h, node, lane);
        float v0 = fmaxf(acc.x + b4.x, 0.0f);
        float v1 = fmaxf(acc.y + b4.y, 0.0f);
        float v2 = fmaxf(acc.z + b4.z, 0.0f);
        float v3 = fmaxf(acc.w + b4.w, 0.0f);
        m0 = fmaxf(m0, v0); m1 = fmaxf(m1, v1);
        m2 = fmaxf(m2, v2); m3 = fmaxf(m3, v3);
        s0 += v0; q0 += v0 * v0;
        s1 += v1; q1 += v1 * v1;
        s2 += v2; q2 += v2 * v2;
        s3 += v3; q3 += v3 * v3;
    }
    if (cur_g >= 0) {
        int* mb = g_maxb + cur_g * F + d;
        atomicMax(mb + 0, __float_as_int(m0));
        atomicMax(mb + 1, __float_as_int(m1));
        atomicMax(mb + 2, __float_as_int(m2));
        atomicMax(mb + 3, __float_as_int(m3));
    }
    atomicAdd(&ss[d + 0], s0);  atomicAdd(&ss[128 + d + 0], q0);
    atomicAdd(&ss[d + 1], s1);  atomicAdd(&ss[128 + d + 1], q1);
    atomicAdd(&ss[d + 2], s2);  atomicAdd(&ss[128 + d + 2], q2);
    atomicAdd(&ss[d + 3], s3);  atomicAdd(&ss[128 + d + 3], q3);
    __syncthreads();
    if (tid < 256) atomicAdd(&sums[tid], ss[tid]);
}

// out = BN2(max) with affine computed inline from raw sums
__global__ void pool_out_kernel(const float* __restrict__ sums2, const float* __restrict__ g2,
                                const float* __restrict__ be2, float* __restrict__ out)
{
    int idx = blockIdx.x * blockDim.x + threadIdx.x;
    if (idx >= NG * F) return;
    int d = idx & 127;
    const float invM = 1.0f / (float)NNODES;
    float m   = sums2[d] * invM;
    float var = sums2[F + d] * invM - m * m;
    float sc  = g2[d] * rsqrtf(var + BN_EPS);
    float v   = __int_as_float(g_maxb[idx]);
    out[idx]  = fmaf(sc, v, be2[d] - sc * m);
}

// ================= cell branch helpers ==========================================
__global__ void bn_stats_kernel(const float* __restrict__ in, float* __restrict__ sums, int M) {
    int d = threadIdx.x;
    float s = 0.0f, q = 0.0f;
    for (int r = blockIdx.x; r < M; r += gridDim.x) {
        float v = in[(size_t)r * F + d];
        s += v; q += v * v;
    }
    atomicAdd(&sums[d], s);
    atomicAdd(&sums[F + d], q);
}

__global__ void bn_apply_kernel(const float* __restrict__ in, const float* __restrict__ sums,
                                const float* __restrict__ gamma, const float* __restrict__ beta,
                                float* __restrict__ out, int M)
{
    int i = blockIdx.x * blockDim.x + threadIdx.x;
    if (i >= M * F) return;
    int d = i & 127;
    float invM = 1.0f / (float)M;
    float m   = sums[d] * invM;
    float var = sums[F + d] * invM - m * m;
    out[i] = gamma[d] * (in[i] - m) * rsqrtf(var + BN_EPS) + beta[d];
}

__global__ __launch_bounds__(256) void gemm128(
    const float* __restrict__ A, const float* __restrict__ B,
    const float* __restrict__ bias, float* __restrict__ C,
    int M, int K, int act)
{
    __shared__ float As[16][132];
    __shared__ float Bs[16][128];
    const int tid = threadIdx.x;
    const int m0  = blockIdx.x * 128;
    const int tn  = tid & 15;
    const int tm  = tid >> 4;
    float acc[8][8];
#pragma unroll
    for (int i = 0; i < 8; i++)
#pragma unroll
        for (int j = 0; j < 8; j++) acc[i][j] = 0.0f;
    const int arow = tid >> 4, acol = tid & 15;
    const int brow = tid >> 7, bcol = tid & 127;
    for (int kk = 0; kk < K; kk += 16) {
#pragma unroll
        for (int p = 0; p < 8; p++) {
            int m = p * 16 + arow, gk = kk + acol, gm = m0 + m;
            float v = 0.0f;
            if (gm < M && gk < K) v = A[(size_t)gm * K + gk];
            As[acol][m] = v;
        }
#pragma unroll
        for (int q = 0; q < 8; q++) {
            int k = q * 2 + brow, gk = kk + k;
            Bs[k][bcol] = (gk < K) ? B[(size_t)gk * 128 + bcol] : 0.0f;
        }
        __syncthreads();
#pragma unroll
        for (int k = 0; k < 16; k++) {
            float4 a0 = *(const float4*)&As[k][tm * 8];
            float4 a1 = *(const float4*)&As[k][tm * 8 + 4];
            float4 b0 = *(const float4*)&Bs[k][tn * 8];
            float4 b1 = *(const float4*)&Bs[k][tn * 8 + 4];
            float a[8] = {a0.x, a0.y, a0.z, a0.w, a1.x, a1.y, a1.z, a1.w};
            float b[8] = {b0.x, b0.y, b0.z, b0.w, b1.x, b1.y, b1.z, b1.w};
#pragma unroll
            for (int i = 0; i < 8; i++)
#pragma unroll
                for (int j = 0; j < 8; j++)
                    acc[i][j] = fmaf(a[i], b[j], acc[i][j]);
        }
        __syncthreads();
    }
#pragma unroll
    for (int i = 0; i < 8; i++) {
        int gm = m0 + tm * 8 + i;
        if (gm >= M) continue;
        float o[8];
#pragma unroll
        for (int j = 0; j < 8; j++) {
            float v = acc[i][j] + bias[tn * 8 + j];
            if (act == 1)      v = fmaxf(v, 0.0f);
            else if (act == 2) v = tanhf(v);
            o[j] = v;
        }
        float4* cp = (float4*)&C[(size_t)gm * 128 + tn * 8];
        cp[0] = make_float4(o[0], o[1], o[2], o[3]);
        cp[1] = make_float4(o[4], o[5], o[6], o[7]);
    }
}

// ================= launch ========================================================
extern "C" void kernel_launch(void* const* d_in, const int* in_sizes, int n_in,
                              void* d_out, int out_size)
{
    const float* x      = (const float*)d_in[0];
    const int*   eidx   = (const int*)  d_in[1];
    const int*   ibatch = (const int*)  d_in[2];
    const float* gexpr  = (const float*)d_in[3];
    const float* W1  = (const float*)d_in[4];
    const float* b1  = (const float*)d_in[5];
    const float* g1  = (const float*)d_in[6];
    const float* be1 = (const float*)d_in[7];
    const float* W2  = (const float*)d_in[8];
    const float* b2  = (const float*)d_in[9];
    const float* g2  = (const float*)d_in[10];
    const float* be2 = (const float*)d_in[11];
    const float* Wc1 = (const float*)d_in[12];
    const float* bc1 = (const float*)d_in[13];
    const float* gc  = (const float*)d_in[14];
    const float* bec = (const float*)d_in[15];
    const float* Wc2 = (const float*)d_in[16];
    const float* bc2 = (const float*)d_in[17];
    float* out = (float*)d_out;

    const int* src = eidx;
    const int* dst = eidx + NEDGES;

    float* bufA; cudaGetSymbolAddress((void**)&bufA, g_bufA);
    float* bufB; cudaGetSymbolAddress((void**)&bufB, g_bufB);
    float* cell; cudaGetSymbolAddress((void**)&cell, g_cell);
    float* sums; cudaGetSymbolAddress((void**)&sums, g_sums);
    float* cst;  cudaGetSymbolAddress((void**)&cst,  g_const);
    __nv_bfloat16 *w1hi, *w1lo, *w2hi, *w2lo;
    cudaGetSymbolAddress((void**)&w1hi, g_w1hi);
    cudaGetSymbolAddress((void**)&w1lo, g_w1lo);
    cudaGetSymbolAddress((void**)&w2hi, g_w2hi);
    cudaGetSymbolAddress((void**)&w2lo, g_w2lo);
    __half* hbuf = (__half*)bufA;

    cudaFuncSetAttribute(gemm_mma,  cudaFuncAttributeMaxDynamicSharedMemorySize, MMA_SMEM);
    cudaFuncSetAttribute(gemm_lite, cudaFuncAttributeMaxDynamicSharedMemorySize, LITE_SMEM);

    static cudaStream_t s_csr = nullptr, s_cell = nullptr;
    static cudaEvent_t ev_root = nullptr, ev_csr = nullptr, ev_cell = nullptr;
    if (!s_csr) {
        cudaStreamCreateWithFlags(&s_csr,  cudaStreamNonBlocking);
        cudaStreamCreateWithFlags(&s_cell, cudaStreamNonBlocking);
        cudaEventCreateWithFlags(&ev_root, cudaEventDisableTiming);
        cudaEventCreateWithFlags(&ev_csr,  cudaEventDisableTiming);
        cudaEventCreateWithFlags(&ev_cell, cudaEventDisableTiming);
    }

    const int T = 256;
    int gN  = (NNODES + T - 1) / T;
    int gE  = (NEDGES + T - 1) / T;
    int gGF = (NG * F + T - 1) / T;
    int gGather = (NNODES + 127) / 128;   // 1563 blocks x 16 warps x 8 nodes
    int gTile   = (NNODES + 127) / 128;   // 1563
    int gGemmG  = (NG + 127) / 128;

    // ---- fork
    cudaEventRecord(ev_root, 0);
    cudaStreamWaitEvent(s_csr,  ev_root, 0);
    cudaStreamWaitEvent(s_cell, ev_root, 0);

    // submissions 1-4 (gemm_mma stays in ncu slot)
    init_kernel<<<gN, T, 0, s_csr>>>();
    deg_kernel<<<gE, T, 0, s_csr>>>(dst);
    wprep1_kernel<<<(F * F + 255) / 256, 256>>>(W1);
    gemm_mma<<<gTile, 256, MMA_SMEM>>>(x, NNODES, w1hi, w1lo, hbuf);

    // ---- rest of CSR branch
    scan1_kernel<<<NBLK, 256, 0, s_csr>>>();
    scan2_kernel<<<1, 1024, 0, s_csr>>>();
    scan3_kernel<<<gN, T, 0, s_csr>>>();
    fill_kernel<<<gE, T, 0, s_csr>>>(src, dst);
    cudaEventRecord(ev_csr, s_csr);

    // ---- cell branch
    zero_cell_sums<<<1, 256, 0, s_cell>>>();
    gemm128<<<gGemmG, 256, 0, s_cell>>>(gexpr, Wc1, bc1, cell, NG, DCELL, 2);
    bn_stats_kernel<<<512, 128, 0, s_cell>>>(cell, sums + 512, NG);
    bn_apply_kernel<<<gGF, T, 0, s_cell>>>(cell, sums + 512, gc, bec, cell, NG);
    gemm128<<<gGemmG, 256, 0, s_cell>>>(cell, Wc2, bc2, out + (size_t)NG * F, NG, 128, 1);
    cudaEventRecord(ev_cell, s_cell);

    // ---- main: join CSR, aggregation pipeline
    cudaStreamWaitEvent(0, ev_csr, 0);
    gather_split_kernel<<<gGather, 512>>>(hbuf, (uint4*)bufB, b1, sums + 0);
    wprep2_kernel<<<128, 128>>>(W2, sums + 0, g1, be1);

    gemm_lite<<<gTile * 2, 256, LITE_SMEM>>>((const uint2*)bufB, NNODES, w2hi, w2lo, cst, hbuf);
    gather_pool_kernel<<<gGather, 512>>>(hbuf, ibatch, b2, sums + 256);
    pool_out_kernel<<<gGF, T>>>(sums + 256, g2, be2, out);

    // ---- join cell branch
    cudaStreamWaitEvent(0, ev_cell, 0);
}

// round 15
// speedup vs baseline: 1.1425x; 1.0001x over previous
#include <cuda_runtime.h>
#include <cuda_bf16.h>
#include <cuda_fp16.h>
#include <math.h>
#include <cstdint>

#define NNODES 200000
#define NEDGES 800000
#define NG     4096
#define DCELL  954
#define F      128
#define BN_EPS 1e-5f
#define NBLK   782          // ceil(NNODES/256)

// ================= mma.sync helpers =============================================
__device__ __forceinline__ uint32_t smem_to_u32(const void* p) {
    uint32_t a;
    asm("{ .reg .u64 t; cvta.to.shared.u64 t, %1; cvt.u32.u64 %0, t; }" : "=r"(a) : "l"(p));
    return a;
}

#define LDSM_X4(r, addr) \
    asm volatile("ldmatrix.sync.aligned.m8n8.x4.shared.b16 {%0,%1,%2,%3}, [%4];" \
        : "=r"((r)[0]), "=r"((r)[1]), "=r"((r)[2]), "=r"((r)[3]) : "r"(addr))

#define MMA16816(c, a0, a1, a2, a3, b0, b1) \
    asm volatile("mma.sync.aligned.m16n8k16.row.col.f32.bf16.bf16.f32 " \
        "{%0,%1,%2,%3}, {%4,%5,%6,%7}, {%8,%9}, {%0,%1,%2,%3};" \
        : "+f"((c)[0]), "+f"((c)[1]), "+f"((c)[2]), "+f"((c)[3]) \
        : "r"(a0), "r"(a1), "r"(a2), "r"(a3), "r"(b0), "r"(b1))

__device__ __forceinline__ void splitpack(float x, float y, uint32_t& hi, uint32_t& lo) {
    __nv_bfloat16 hx = __float2bfloat16(x), hy = __float2bfloat16(y);
    __nv_bfloat162 h2 = __halves2bfloat162(hx, hy);
    hi = *reinterpret_cast<uint32_t*>(&h2);
    __nv_bfloat162 l2 = __halves2bfloat162(__float2bfloat16(x - __bfloat162float(hx)),
                                           __float2bfloat16(y - __bfloat162float(hy)));
    lo = *reinterpret_cast<uint32_t*>(&l2);
}

__device__ __forceinline__ float4 h4f(uint2 u) {
    __half2 a = *reinterpret_cast<__half2*>(&u.x);
    __half2 b = *reinterpret_cast<__half2*>(&u.y);
    float2 fa = __half22float2(a), fb = __half22float2(b);
    return make_float4(fa.x, fa.y, fb.x, fb.y);
}

// ================= scratch =======================================================
__device__ float g_bufA[(size_t)NNODES * F];    // h1/h2 as fp16 (reused)
__device__ float g_bufB[(size_t)NNODES * F];    // R split: uint2[node*64+c]={hi,lo}
__device__ float g_dinv[NNODES];
__device__ int   g_deg[NNODES];
__device__ int   g_cursor[NNODES];
__device__ int   g_csr_ptr[NNODES + 1];
__device__ int   g_csr_src[NEDGES];
__device__ float g_csr_w[NEDGES];               // precomputed dinv[dst]*dinv[src]
__device__ int   g_blocksums[1024];
__device__ int   g_blockoff[1024];
__device__ float g_cell[(size_t)NG * F];
__device__ float g_sums[3 * 2 * F];
__device__ float g_const[F];
__device__ int   g_maxb[NG * F];
__device__ __nv_bfloat16 g_w1hi[F * F], g_w1lo[F * F], g_w2hi[F * F], g_w2lo[F * F];

// ================= init / degree / CSR ==========================================
__global__ void init_kernel() {
    int i = blockIdx.x * blockDim.x + threadIdx.x;
    if (i < NNODES) { g_deg[i] = 0; g_cursor[i] = 0; }
    if (i < 2 * 2 * F) g_sums[i] = 0.0f;
    for (int j = i; j < NG * F; j += gridDim.x * blockDim.x) g_maxb[j] = 0;
}
__global__ void zero_cell_sums() {
    g_sums[512 + threadIdx.x] = 0.0f;
}
__global__ void deg_kernel(const int* __restrict__ dst) {
    int e = blockIdx.x * blockDim.x + threadIdx.x;
    if (e < NEDGES) atomicAdd(&g_deg[dst[e]], 1);
}
__global__ void scan1_kernel() {
    __shared__ int sh[256];
    int i = blockIdx.x * 256 + threadIdx.x;
    int v = (i < NNODES) ? g_deg[i] : 0;
    if (i < NNODES) g_dinv[i] = rsqrtf((float)v + 1.0f);
    sh[threadIdx.x] = v;
    __syncthreads();
#pragma unroll
    for (int off = 1; off < 256; off <<= 1) {
        int t = (threadIdx.x >= off) ? sh[threadIdx.x - off] : 0;
        __syncthreads();
        sh[threadIdx.x] += t;
        __syncthreads();
    }
    if (i < NNODES) g_csr_ptr[i] = sh[threadIdx.x] - v;
    if (threadIdx.x == 255) g_blocksums[blockIdx.x] = sh[255];
}
__global__ void scan2_kernel() {
    __shared__ int sh[1024];
    int t = threadIdx.x;
    int v = (t < NBLK) ? g_blocksums[t] : 0;
    sh[t] = v;
    __syncthreads();
#pragma unroll
    for (int off = 1; off < 1024; off <<= 1) {
        int u = (t >= off) ? sh[t - off] : 0;
        __syncthreads();
        sh[t] += u;
        __syncthreads();
    }
    if (t < NBLK) g_blockoff[t] = sh[t] - v;
}
__global__ void scan3_kernel() {
    int i = blockIdx.x * blockDim.x + threadIdx.x;
    if (i < NNODES) g_csr_ptr[i] += g_blockoff[i >> 8];
    if (i == 0) g_csr_ptr[NNODES] = NEDGES;
}
// fill edge list AND precomputed norm weight (dinv ready after scan1)
__global__ void fill_kernel(const int* __restrict__ src, const int* __restrict__ dst) {
    int e = blockIdx.x * blockDim.x + threadIdx.x;
    if (e >= NEDGES) return;
    int d = dst[e];
    int s = src[e];
    int pos = g_csr_ptr[d] + atomicAdd(&g_cursor[d], 1);
    g_csr_src[pos] = s;
    g_csr_w[pos]   = g_dinv[d] * g_dinv[s];
}

// ================= weight prep ===================================================
__global__ void wprep1_kernel(const float* __restrict__ W1) {
    int i = blockIdx.x * blockDim.x + threadIdx.x;
    if (i >= F * F) return;
    int k = i >> 7, n = i & 127;
    float v = W1[i];
    __nv_bfloat16 h = __float2bfloat16(v);
    g_w1hi[n * F + k] = h;
    g_w1lo[n * F + k] = __float2bfloat16(v - __bfloat162float(h));
}

// fold BN1 into W2, affine computed inline from raw sums
__global__ void wprep2_kernel(const float* __restrict__ W2, const float* __restrict__ sums,
                              const float* __restrict__ g1, const float* __restrict__ be1) {
    __shared__ float red[128];
    int n = blockIdx.x, k = threadIdx.x;
    const float invM = 1.0f / (float)NNODES;
    float m   = sums[k] * invM;
    float var = sums[F + k] * invM - m * m;
    float sc  = g1[k] * rsqrtf(var + BN_EPS);
    float sh  = be1[k] - sc * m;
    float w   = W2[k * 128 + n];
    float ws  = w * sc;
    __nv_bfloat16 h = __float2bfloat16(ws);
    g_w2hi[n * 128 + k] = h;
    g_w2lo[n * 128 + k] = __float2bfloat16(ws - __bfloat162float(h));
    red[k] = sh * w;
    __syncthreads();
#pragma unroll
    for (int off = 64; off; off >>= 1) {
        if (k < off) red[k] += red[k + off];
        __syncthreads();
    }
    if (k == 0) g_const[n] = red[0];
}

// ================= GEMM-1: h1(fp16) = split3(x fp32) @ W1 (BM=128) ==============
#define AST    136
#define SW_HI  0
#define SW_LO  (128 * AST * 2)
#define MMA_SMEM (2 * 128 * AST * 2)   // 69632

__global__ void __launch_bounds__(256, 2)
gemm_mma(const float* __restrict__ A, int M,
         const __nv_bfloat16* __restrict__ Whi, const __nv_bfloat16* __restrict__ Wlo,
         __half* __restrict__ C)
{
    extern __shared__ char sm[];
    const int tid  = threadIdx.x;
    const int lane = tid & 31;
    const int wid  = tid >> 5;
    const int m0   = blockIdx.x * 128;

    for (int i = tid; i < 2048; i += 256) {
        int n = i >> 4, kg = i & 15;
        *(uint4*)(sm + SW_HI + ((size_t)n * AST + kg * 8) * 2) = *(const uint4*)(Whi + n * 128 + kg * 8);
        *(uint4*)(sm + SW_LO + ((size_t)n * AST + kg * 8) * 2) = *(const uint4*)(Wlo + n * 128 + kg * 8);
    }
    __syncthreads();

    const int wm = (wid & 3) * 32;
    const int wn = (wid >> 2) * 64;
    uint32_t sb  = smem_to_u32(sm);
    uint32_t brw = wn + (lane >> 4) * 8 + (lane & 7);
    uint32_t bHi = sb + SW_HI + ((brw * AST + ((lane >> 3) & 1) * 8) << 1);
    uint32_t bLo = bHi + SW_LO;

    const int r0 = lane >> 2;
    const int c0 = (lane & 3) * 2;
    const int rowA = m0 + wm + r0;
    const bool okA[2][2] = {{rowA < M, rowA + 8 < M}, {rowA + 16 < M, rowA + 24 < M}};

    float c[2][8][4];
#pragma unroll
    for (int f = 0; f < 2; f++)
#pragma unroll
        for (int j = 0; j < 8; j++)
#pragma unroll
            for (int e = 0; e < 4; e++) c[f][j][e] = 0.0f;

    const float2 Z2 = make_float2(0.f, 0.f);
    float2 raw[2][4];
    {
#pragma unroll
        for (int f = 0; f < 2; f++) {
            const float* p0 = A + (size_t)(rowA + f * 16) * 128 + c0;
            raw[f][0] = okA[f][0] ? *(const float2*)p0          : Z2;
            raw[f][1] = okA[f][1] ? *(const float2*)(p0 + 1024) : Z2;
            raw[f][2] = okA[f][0] ? *(const float2*)(p0 + 8)    : Z2;
            raw[f][3] = okA[f][1] ? *(const float2*)(p0 + 1032) : Z2;
        }
    }

    uint32_t ah[2][4], al[2][4];
    auto do_split = [&](float2 (&rw)[2][4]) {
#pragma unroll
        for (int f = 0; f < 2; f++) {
            splitpack(rw[f][0].x, rw[f][0].y, ah[f][0], al[f][0]);
            splitpack(rw[f][1].x, rw[f][1].y, ah[f][1], al[f][1]);
            splitpack(rw[f][2].x, rw[f][2].y, ah[f][2], al[f][2]);
            splitpack(rw[f][3].x, rw[f][3].y, ah[f][3], al[f][3]);
        }
    };
    do_split(raw);

#pragma unroll
    for (int ks = 0; ks < 8; ks++) {
        float2 rn[2][4];
        if (ks < 7) {
            const int kc = (ks + 1) * 16 + c0;
#pragma unroll
            for (int f = 0; f < 2; f++) {
                const float* p0 = A + (size_t)(rowA + f * 16) * 128 + kc;
                rn[f][0] = okA[f][0] ? *(const float2*)p0          : Z2;
                rn[f][1] = okA[f][1] ? *(const float2*)(p0 + 1024) : Z2;
                rn[f][2] = okA[f][0] ? *(const float2*)(p0 + 8)    : Z2;
                rn[f][3] = okA[f][1] ? *(const float2*)(p0 + 1032) : Z2;
            }
        }
#pragma unroll
        for (int p = 0; p < 4; p++) {
            uint32_t bh[4], bl[4];
            LDSM_X4(bh, bHi + ks * 32 + p * 16 * AST * 2);
            LDSM_X4(bl, bLo + ks * 32 + p * 16 * AST * 2);
#pragma unroll
            for (int f = 0; f < 2; f++)
#pragma unroll
                for (int q = 0; q < 2; q++) {
                    int j = p * 2 + q;
                    MMA16816(c[f][j], ah[f][0], ah[f][1], ah[f][2], ah[f][3], bh[q * 2], bh[q * 2 + 1]);
                    MMA16816(c[f][j], al[f][0], al[f][1], al[f][2], al[f][3], bh[q * 2], bh[q * 2 + 1]);
                    MMA16816(c[f][j], ah[f][0], ah[f][1], ah[f][2], ah[f][3], bl[q * 2], bl[q * 2 + 1]);
                }
        }
        if (ks < 7) do_split(rn);
    }

    const int cc = (lane & 3) * 2;
#pragma unroll
    for (int f = 0; f < 2; f++) {
        int row = m0 + wm + f * 16 + r0;
#pragma unroll
        for (int j = 0; j < 8; j++) {
            int col = wn + j * 8 + cc;
            if (row < M)
                *(__half2*)(C + (size_t)row * 128 + col) = __floats2half2_rn(c[f][j][0], c[f][j][1]);
            if (row + 8 < M)
                *(__half2*)(C + (size_t)(row + 8) * 128 + col) = __floats2half2_rn(c[f][j][2], c[f][j][3]);
        }
    }
}

// ================= GEMM-2 lite: h2(fp16) = (Rhi+Rlo) @ W2' + const (BM=128) =====
#define LCONST (2 * 128 * AST * 2)
#define LITE_SMEM (LCONST + 512)

__global__ void __launch_bounds__(256, 2)
gemm_lite(const uint2* __restrict__ Rq, int M,
          const __nv_bfloat16* __restrict__ Whi, const __nv_bfloat16* __restrict__ Wlo,
          const float* __restrict__ cst, __half* __restrict__ C)
{
    extern __shared__ char sm[];
    float* csm = (float*)(sm + LCONST);
    const int tid  = threadIdx.x;
    const int lane = tid & 31;
    const int wid  = tid >> 5;
    const int m0   = blockIdx.x * 128;

    for (int i = tid; i < 2048; i += 256) {
        int n = i >> 4, kg = i & 15;
        *(uint4*)(sm + SW_HI + ((size_t)n * AST + kg * 8) * 2) = *(const uint4*)(Whi + n * 128 + kg * 8);
        *(uint4*)(sm + SW_LO + ((size_t)n * AST + kg * 8) * 2) = *(const uint4*)(Wlo + n * 128 + kg * 8);
    }
    if (tid < 128) csm[tid] = cst[tid];
    __syncthreads();

    const int wm = (wid & 3) * 32;
    const int wn = (wid >> 2) * 64;
    uint32_t sb  = smem_to_u32(sm);
    uint32_t brw = wn + (lane >> 4) * 8 + (lane & 7);
    uint32_t bHi = sb + SW_HI + ((brw * AST + ((lane >> 3) & 1) * 8) << 1);
    uint32_t bLo = bHi + SW_LO;

    const int r0 = lane >> 2;
    const int q0 = lane & 3;
    const int rowA = m0 + wm + r0;
    const bool okA[2][2] = {{rowA < M, rowA + 8 < M}, {rowA + 16 < M, rowA + 24 < M}};

    float c[2][8][4];
#pragma unroll
    for (int f = 0; f < 2; f++)
#pragma unroll
        for (int j = 0; j < 8; j++)
#pragma unroll
            for (int e = 0; e < 4; e++) c[f][j][e] = 0.0f;

    const uint2 ZU = make_uint2(0u, 0u);
    auto loadA = [&](int ks, uint2 (&fr)[2][4]) {
        int cb = ks * 8 + q0;
#pragma unroll
        for (int f = 0; f < 2; f++) {
            const uint2* p = Rq + (size_t)(rowA + f * 16) * 64 + cb;
            fr[f][0] = okA[f][0] ? p[0]   : ZU;
            fr[f][1] = okA[f][1] ? p[512] : ZU;
            fr[f][2] = okA[f][0] ? p[4]   : ZU;
            fr[f][3] = okA[f][1] ? p[516] : ZU;
        }
    };

    uint2 cur[2][4], nxt[2][4];
    loadA(0, cur);

#pragma unroll
    for (int ks = 0; ks < 8; ks++) {
        if (ks < 7) loadA(ks + 1, nxt);
#pragma unroll
        for (int p = 0; p < 4; p++) {
            uint32_t bh[4], bl[4];
            LDSM_X4(bh, bHi + ks * 32 + p * 16 * AST * 2);
            LDSM_X4(bl, bLo + ks * 32 + p * 16 * AST * 2);
#pragma unroll
            for (int f = 0; f < 2; f++)
#pragma unroll
                for (int q = 0; q < 2; q++) {
                    int j = p * 2 + q;
                    MMA16816(c[f][j], cur[f][0].x, cur[f][1].x, cur[f][2].x, cur[f][3].x, bh[q * 2], bh[q * 2 + 1]);
                    MMA16816(c[f][j], cur[f][0].y, cur[f][1].y, cur[f][2].y, cur[f][3].y, bh[q * 2], bh[q * 2 + 1]);
                    MMA16816(c[f][j], cur[f][0].x, cur[f][1].x, cur[f][2].x, cur[f][3].x, bl[q * 2], bl[q * 2 + 1]);
                }
        }
        if (ks < 7) {
#pragma unroll
            for (int f = 0; f < 2; f++)
#pragma unroll
                for (int i = 0; i < 4; i++) cur[f][i] = nxt[f][i];
        }
    }

    const int cc = (lane & 3) * 2;
#pragma unroll
    for (int f = 0; f < 2; f++) {
        int row = m0 + wm + f * 16 + r0;
#pragma unroll
        for (int j = 0; j < 8; j++) {
            int col = wn + j * 8 + cc;
            float k0 = csm[col], k1 = csm[col + 1];
            if (row < M)
                *(__half2*)(C + (size_t)row * 128 + col) = __floats2half2_rn(c[f][j][0] + k0, c[f][j][1] + k1);
            if (row + 8 < M)
                *(__half2*)(C + (size_t)(row + 8) * 128 + col) = __floats2half2_rn(c[f][j][2] + k0, c[f][j][3] + k1);
        }
    }
}

// ================= gather core (CSR, fp16 rows, precomputed edge weights) ========
__device__ __forceinline__ float4 gather_acc(const __half* __restrict__ h, int node, int lane) {
    int beg = g_csr_ptr[node];
    int end = g_csr_ptr[node + 1];
    float di = g_dinv[node];
    const uint2* hv = (const uint2*)h;
    float4 acc = h4f(hv[(size_t)node * 32 + lane]);
    float sn = di * di;
    acc.x *= sn; acc.y *= sn; acc.z *= sn; acc.w *= sn;
    int e = beg;
    for (; e + 3 < end; e += 4) {
        int s0 = __ldg(&g_csr_src[e]);
        int s1 = __ldg(&g_csr_src[e + 1]);
        int s2 = __ldg(&g_csr_src[e + 2]);
        int s3 = __ldg(&g_csr_src[e + 3]);
        float n0 = __ldg(&g_csr_w[e]);
        float n1 = __ldg(&g_csr_w[e + 1]);
        float n2 = __ldg(&g_csr_w[e + 2]);
        float n3 = __ldg(&g_csr_w[e + 3]);
        float4 v0 = h4f(hv[(size_t)s0 * 32 + lane]);
        float4 v1 = h4f(hv[(size_t)s1 * 32 + lane]);
        float4 v2 = h4f(hv[(size_t)s2 * 32 + lane]);
        float4 v3 = h4f(hv[(size_t)s3 * 32 + lane]);
        acc.x = fmaf(v0.x, n0, acc.x); acc.y = fmaf(v0.y, n0, acc.y);
        acc.z = fmaf(v0.z, n0, acc.z); acc.w = fmaf(v0.w, n0, acc.w);
        acc.x = fmaf(v1.x, n1, acc.x); acc.y = fmaf(v1.y, n1, acc.y);
        acc.z = fmaf(v1.z, n1, acc.z); acc.w = fmaf(v1.w, n1, acc.w);
        acc.x = fmaf(v2.x, n2, acc.x); acc.y = fmaf(v2.y, n2, acc.y);
        acc.z = fmaf(v2.z, n2, acc.z); acc.w = fmaf(v2.w, n2, acc.w);
        acc.x = fmaf(v3.x, n3, acc.x); acc.y = fmaf(v3.y, n3, acc.y);
        acc.z = fmaf(v3.z, n3, acc.z); acc.w = fmaf(v3.w, n3, acc.w);
    }
    for (; e < end; e++) {
        int s0 = __ldg(&g_csr_src[e]);
        float n0 = __ldg(&g_csr_w[e]);
        float4 v0 = h4f(hv[(size_t)s0 * 32 + lane]);
        acc.x = fmaf(v0.x, n0, acc.x); acc.y = fmaf(v0.y, n0, acc.y);
        acc.z = fmaf(v0.z, n0, acc.z); acc.w = fmaf(v0.w, n0, acc.w);
    }
    return acc;
}

#define NPW 8   // nodes per warp

// gather-1: warp owns 8 consecutive nodes; BN sums in REGISTERS (R12 shape)
// launch_bounds(512,2): cap regs at 64 -> 2 blocks = 32 warps resident per SM
__global__ void __launch_bounds__(512, 2)
gather_split_kernel(const __half* __restrict__ h, uint4* __restrict__ Rq4,
                    const float* __restrict__ bias, float* __restrict__ sums)
{
    __shared__ float ss[256];
    int tid = threadIdx.x;                    // 512 threads = 16 warps = 128 nodes
    if (tid < 256) ss[tid] = 0.0f;
    __syncthreads();

    int lane = tid & 31;
    int base = blockIdx.x * 128 + (tid >> 5) * NPW;
    int d = lane * 4;
    float4 b4 = make_float4(bias[d], bias[d + 1], bias[d + 2], bias[d + 3]);

    float s0 = 0, s1 = 0, s2 = 0, s3 = 0, q0 = 0, q1 = 0, q2 = 0, q3 = 0;
    for (int i = 0; i < NPW; i++) {
        int node = base + i;
        if (node >= NNODES) break;
        float4 acc = gather_acc(h, node, lane);
        float v0 = fmaxf(acc.x + b4.x, 0.0f);
        float v1 = fmaxf(acc.y + b4.y, 0.0f);
        float v2 = fmaxf(acc.z + b4.z, 0.0f);
        float v3 = fmaxf(acc.w + b4.w, 0.0f);
        uint32_t h01, l01, h23, l23;
        splitpack(v0, v1, h01, l01);
        splitpack(v2, v3, h23, l23);
        Rq4[(size_t)node * 32 + lane] = make_uint4(h01, l01, h23, l23);
        s0 += v0; q0 += v0 * v0;
        s1 += v1; q1 += v1 * v1;
        s2 += v2; q2 += v2 * v2;
        s3 += v3; q3 += v3 * v3;
    }
    atomicAdd(&ss[d + 0], s0);  atomicAdd(&ss[128 + d + 0], q0);
    atomicAdd(&ss[d + 1], s1);  atomicAdd(&ss[128 + d + 1], q1);
    atomicAdd(&ss[d + 2], s2);  atomicAdd(&ss[128 + d + 2], q2);
    atomicAdd(&ss[d + 3], s3);  atomicAdd(&ss[128 + d + 3], q3);
    __syncthreads();
    if (tid < 256) atomicAdd(&sums[tid], ss[tid]);
}

// gather-2: register BN sums + register pool-max flushed on graph transitions
__global__ void __launch_bounds__(512, 2)
gather_pool_kernel(const __half* __restrict__ h, const int* __restrict__ ibatch,
                   const float* __restrict__ bias, float* __restrict__ sums)
{
    __shared__ float ss[256];
    int tid = threadIdx.x;
    if (tid < 256) ss[tid] = 0.0f;
    __syncthreads();

    int lane = tid & 31;
    int base = blockIdx.x * 128 + (tid >> 5) * NPW;
    int d = lane * 4;
    float4 b4 = make_float4(bias[d], bias[d + 1], bias[d + 2], bias[d + 3]);

    float s0 = 0, s1 = 0, s2 = 0, s3 = 0, q0 = 0, q1 = 0, q2 = 0, q3 = 0;
    float m0 = 0, m1 = 0, m2 = 0, m3 = 0;
    int cur_g = -1;

    for (int i = 0; i < NPW; i++) {
        int node = base + i;
        if (node >= NNODES) break;
        int g = 0;
        if (lane == 0) g = __ldg(&ibatch[node]);
        g = __shfl_sync(0xffffffffu, g, 0);
        if (g != cur_g) {
            if (cur_g >= 0) {
                int* mb = g_maxb + cur_g * F + d;
                atomicMax(mb + 0, __float_as_int(m0));
                atomicMax(mb + 1, __float_as_int(m1));
                atomicMax(mb + 2, __float_as_int(m2));
                atomicMax(mb + 3, __float_as_int(m3));
            }
            cur_g = g;
            m0 = m1 = m2 = m3 = 0.0f;   // values are relu >= 0
        }
        float4 acc = gather_acc(h, node, lane);
        float v0 = fmaxf(acc.x + b4.x, 0.0f);
        float v1 = fmaxf(acc.y + b4.y, 0.0f);
        float v2 = fmaxf(acc.z + b4.z, 0.0f);
        float v3 = fmaxf(acc.w + b4.w, 0.0f);
        m0 = fmaxf(m0, v0); m1 = fmaxf(m1, v1);
        m2 = fmaxf(m2, v2); m3 = fmaxf(m3, v3);
        s0 += v0; q0 += v0 * v0;
        s1 += v1; q1 += v1 * v1;
        s2 += v2; q2 += v2 * v2;
        s3 += v3; q3 += v3 * v3;
    }
    if (cur_g >= 0) {
        int* mb = g_maxb + cur_g * F + d;
        atomicMax(mb + 0, __float_as_int(m0));
        atomicMax(mb + 1, __float_as_int(m1));
        atomicMax(mb + 2, __float_as_int(m2));
        atomicMax(mb + 3, __float_as_int(m3));
    }
    atomicAdd(&ss[d + 0], s0);  atomicAdd(&ss[128 + d + 0], q0);
    atomicAdd(&ss[d + 1], s1);  atomicAdd(&ss[128 + d + 1], q1);
    atomicAdd(&ss[d + 2], s2);  atomicAdd(&ss[128 + d + 2], q2);
    atomicAdd(&ss[d + 3], s3);  atomicAdd(&ss[128 + d + 3], q3);
    __syncthreads();
    if (tid < 256) atomicAdd(&sums[tid], ss[tid]);
}

// out = BN2(max) with affine computed inline from raw sums
__global__ void pool_out_kernel(const float* __restrict__ sums2, const float* __restrict__ g2,
                                const float* __restrict__ be2, float* __restrict__ out)
{
    int idx = blockIdx.x * blockDim.x + threadIdx.x;
    if (idx >= NG * F) return;
    int d = idx & 127;
    const float invM = 1.0f / (float)NNODES;
    float m   = sums2[d] * invM;
    float var = sums2[F + d] * invM - m * m;
    float sc  = g2[d] * rsqrtf(var + BN_EPS);
    float v   = __int_as_float(g_maxb[idx]);
    out[idx]  = fmaf(sc, v, be2[d] - sc * m);
}

// ================= cell branch helpers ==========================================
__global__ void bn_stats_kernel(const float* __restrict__ in, float* __restrict__ sums, int M) {
    int d = threadIdx.x;
    float s = 0.0f, q = 0.0f;
    for (int r = blockIdx.x; r < M; r += gridDim.x) {
        float v = in[(size_t)r * F + d];
        s += v; q += v * v;
    }
    atomicAdd(&sums[d], s);
    atomicAdd(&sums[F + d], q);
}

__global__ void bn_apply_kernel(const float* __restrict__ in, const float* __restrict__ sums,
                                const float* __restrict__ gamma, const float* __restrict__ beta,
                                float* __restrict__ out, int M)
{
    int i = blockIdx.x * blockDim.x + threadIdx.x;
    if (i >= M * F) return;
    int d = i & 127;
    float invM = 1.0f / (float)M;
    float m   = sums[d] * invM;
    float var = sums[F + d] * invM - m * m;
    out[i] = gamma[d] * (in[i] - m) * rsqrtf(var + BN_EPS) + beta[d];
}

__global__ __launch_bounds__(256) void gemm128(
    const float* __restrict__ A, const float* __restrict__ B,
    const float* __restrict__ bias, float* __restrict__ C,
    int M, int K, int act)
{
    __shared__ float As[16][132];
    __shared__ float Bs[16][128];
    const int tid = threadIdx.x;
    const int m0  = blockIdx.x * 128;
    const int tn  = tid & 15;
    const int tm  = tid >> 4;
    float acc[8][8];
#pragma unroll
    for (int i = 0; i < 8; i++)
#pragma unroll
        for (int j = 0; j < 8; j++) acc[i][j] = 0.0f;
    const int arow = tid >> 4, acol = tid & 15;
    const int brow = tid >> 7, bcol = tid & 127;
    for (int kk = 0; kk < K; kk += 16) {
#pragma unroll
        for (int p = 0; p < 8; p++) {
            int m = p * 16 + arow, gk = kk + acol, gm = m0 + m;
            float v = 0.0f;
            if (gm < M && gk < K) v = A[(size_t)gm * K + gk];
            As[acol][m] = v;
        }
#pragma unroll
        for (int q = 0; q < 8; q++) {
            int k = q * 2 + brow, gk = kk + k;
            Bs[k][bcol] = (gk < K) ? B[(size_t)gk * 128 + bcol] : 0.0f;
        }
        __syncthreads();
#pragma unroll
        for (int k = 0; k < 16; k++) {
            float4 a0 = *(const float4*)&As[k][tm * 8];
            float4 a1 = *(const float4*)&As[k][tm * 8 + 4];
            float4 b0 = *(const float4*)&Bs[k][tn * 8];
            float4 b1 = *(const float4*)&Bs[k][tn * 8 + 4];
            float a[8] = {a0.x, a0.y, a0.z, a0.w, a1.x, a1.y, a1.z, a1.w};
            float b[8] = {b0.x, b0.y, b0.z, b0.w, b1.x, b1.y, b1.z, b1.w};
#pragma unroll
            for (int i = 0; i < 8; i++)
#pragma unroll
                for (int j = 0; j < 8; j++)
                    acc[i][j] = fmaf(a[i], b[j], acc[i][j]);
        }
        __syncthreads();
    }
#pragma unroll
    for (int i = 0; i < 8; i++) {
        int gm = m0 + tm * 8 + i;
        if (gm >= M) continue;
        float o[8];
#pragma unroll
        for (int j = 0; j < 8; j++) {
            float v = acc[i][j] + bias[tn * 8 + j];
            if (act == 1)      v = fmaxf(v, 0.0f);
            else if (act == 2) v = tanhf(v);
            o[j] = v;
        }
        float4* cp = (float4*)&C[(size_t)gm * 128 + tn * 8];
        cp[0] = make_float4(o[0], o[1], o[2], o[3]);
        cp[1] = make_float4(o[4], o[5], o[6], o[7]);
    }
}

// ================= launch ========================================================
extern "C" void kernel_launch(void* const* d_in, const int* in_sizes, int n_in,
                              void* d_out, int out_size)
{
    const float* x      = (const float*)d_in[0];
    const int*   eidx   = (const int*)  d_in[1];
    const int*   ibatch = (const int*)  d_in[2];
    const float* gexpr  = (const float*)d_in[3];
    const float* W1  = (const float*)d_in[4];
    const float* b1  = (const float*)d_in[5];
    const float* g1  = (const float*)d_in[6];
    const float* be1 = (const float*)d_in[7];
    const float* W2  = (const float*)d_in[8];
    const float* b2  = (const float*)d_in[9];
    const float* g2  = (const float*)d_in[10];
    const float* be2 = (const float*)d_in[11];
    const float* Wc1 = (const float*)d_in[12];
    const float* bc1 = (const float*)d_in[13];
    const float* gc  = (const float*)d_in[14];
    const float* bec = (const float*)d_in[15];
    const float* Wc2 = (const float*)d_in[16];
    const float* bc2 = (const float*)d_in[17];
    float* out = (float*)d_out;

    const int* src = eidx;
    const int* dst = eidx + NEDGES;

    float* bufA; cudaGetSymbolAddress((void**)&bufA, g_bufA);
    float* bufB; cudaGetSymbolAddress((void**)&bufB, g_bufB);
    float* cell; cudaGetSymbolAddress((void**)&cell, g_cell);
    float* sums; cudaGetSymbolAddress((void**)&sums, g_sums);
    float* cst;  cudaGetSymbolAddress((void**)&cst,  g_const);
    __nv_bfloat16 *w1hi, *w1lo, *w2hi, *w2lo;
    cudaGetSymbolAddress((void**)&w1hi, g_w1hi);
    cudaGetSymbolAddress((void**)&w1lo, g_w1lo);
    cudaGetSymbolAddress((void**)&w2hi, g_w2hi);
    cudaGetSymbolAddress((void**)&w2lo, g_w2lo);
    __half* hbuf = (__half*)bufA;

    cudaFuncSetAttribute(gemm_mma,  cudaFuncAttributeMaxDynamicSharedMemorySize, MMA_SMEM);
    cudaFuncSetAttribute(gemm_lite, cudaFuncAttributeMaxDynamicSharedMemorySize, LITE_SMEM);

    static cudaStream_t s_csr = nullptr, s_cell = nullptr;
    static cudaEvent_t ev_root = nullptr, ev_csr = nullptr, ev_cell = nullptr;
    if (!s_csr) {
        cudaStreamCreateWithFlags(&s_csr,  cudaStreamNonBlocking);
        cudaStreamCreateWithFlags(&s_cell, cudaStreamNonBlocking);
        cudaEventCreateWithFlags(&ev_root, cudaEventDisableTiming);
        cudaEventCreateWithFlags(&ev_csr,  cudaEventDisableTiming);
        cudaEventCreateWithFlags(&ev_cell, cudaEventDisableTiming);
    }

    const int T = 256;
    int gN  = (NNODES + T - 1) / T;
    int gE  = (NEDGES + T - 1) / T;
    int gGF = (NG * F + T - 1) / T;
    int gGather = (NNODES + 127) / 128;   // 1563 blocks x 16 warps x 8 nodes
    int gTile   = (NNODES + 127) / 128;   // 1563
    int gGemmG  = (NG + 127) / 128;

    // ---- fork
    cudaEventRecord(ev_root, 0);
    cudaStreamWaitEvent(s_csr,  ev_root, 0);
    cudaStreamWaitEvent(s_cell, ev_root, 0);

    // submissions 1-4 (gemm_mma stays in ncu slot)
    init_kernel<<<gN, T, 0, s_csr>>>();
    deg_kernel<<<gE, T, 0, s_csr>>>(dst);
    wprep1_kernel<<<(F * F + 255) / 256, 256>>>(W1);
    gemm_mma<<<gTile, 256, MMA_SMEM>>>(x, NNODES, w1hi, w1lo, hbuf);

    // ---- rest of CSR branch
    scan1_kernel<<<NBLK, 256, 0, s_csr>>>();
    scan2_kernel<<<1, 1024, 0, s_csr>>>();
    scan3_kernel<<<gN, T, 0, s_csr>>>();
    fill_kernel<<<gE, T, 0, s_csr>>>(src, dst);
    cudaEventRecord(ev_csr, s_csr);

    // ---- cell branch
    zero_cell_sums<<<1, 256, 0, s_cell>>>();
    gemm128<<<gGemmG, 256, 0, s_cell>>>(gexpr, Wc1, bc1, cell, NG, DCELL, 2);
    bn_stats_kernel<<<512, 128, 0, s_cell>>>(cell, sums + 512, NG);
    bn_apply_kernel<<<gGF, T, 0, s_cell>>>(cell, sums + 512, gc, bec, cell, NG);
    gemm128<<<gGemmG, 256, 0, s_cell>>>(cell, Wc2, bc2, out + (size_t)NG * F, NG, 128, 1);
    cudaEventRecord(ev_cell, s_cell);

    // ---- main: join CSR, aggregation pipeline
    cudaStreamWaitEvent(0, ev_csr, 0);
    gather_split_kernel<<<gGather, 512>>>(hbuf, (uint4*)bufB, b1, sums + 0);
    wprep2_kernel<<<128, 128>>>(W2, sums + 0, g1, be1);

    gemm_lite<<<gTile, 256, LITE_SMEM>>>((const uint2*)bufB, NNODES, w2hi, w2lo, cst, hbuf);
    gather_pool_kernel<<<gGather, 512>>>(hbuf, ibatch, b2, sums + 256);
    pool_out_kernel<<<gGF, T>>>(sums + 256, g2, be2, out);

    // ---- join cell branch
    cudaStreamWaitEvent(0, ev_cell, 0);
}

// round 16
// speedup vs baseline: 1.2301x; 1.0766x over previous
#include <cuda_runtime.h>
#include <cuda_bf16.h>
#include <cuda_fp16.h>
#include <math.h>
#include <cstdint>

#define NNODES 200000
#define NEDGES 800000
#define NG     4096
#define DCELL  954
#define F      128
#define BN_EPS 1e-5f
#define NBLK   782          // ceil(NNODES/256)

// ================= mma.sync helpers =============================================
__device__ __forceinline__ uint32_t smem_to_u32(const void* p) {
    uint32_t a;
    asm("{ .reg .u64 t; cvta.to.shared.u64 t, %1; cvt.u32.u64 %0, t; }" : "=r"(a) : "l"(p));
    return a;
}

#define LDSM_X4(r, addr) \
    asm volatile("ldmatrix.sync.aligned.m8n8.x4.shared.b16 {%0,%1,%2,%3}, [%4];" \
        : "=r"((r)[0]), "=r"((r)[1]), "=r"((r)[2]), "=r"((r)[3]) : "r"(addr))

#define MMA16816(c, a0, a1, a2, a3, b0, b1) \
    asm volatile("mma.sync.aligned.m16n8k16.row.col.f32.bf16.bf16.f32 " \
        "{%0,%1,%2,%3}, {%4,%5,%6,%7}, {%8,%9}, {%0,%1,%2,%3};" \
        : "+f"((c)[0]), "+f"((c)[1]), "+f"((c)[2]), "+f"((c)[3]) \
        : "r"(a0), "r"(a1), "r"(a2), "r"(a3), "r"(b0), "r"(b1))

__device__ __forceinline__ void splitpack(float x, float y, uint32_t& hi, uint32_t& lo) {
    __nv_bfloat16 hx = __float2bfloat16(x), hy = __float2bfloat16(y);
    __nv_bfloat162 h2 = __halves2bfloat162(hx, hy);
    hi = *reinterpret_cast<uint32_t*>(&h2);
    __nv_bfloat162 l2 = __halves2bfloat162(__float2bfloat16(x - __bfloat162float(hx)),
                                           __float2bfloat16(y - __bfloat162float(hy)));
    lo = *reinterpret_cast<uint32_t*>(&l2);
}

__device__ __forceinline__ float4 h4f(uint2 u) {
    __half2 a = *reinterpret_cast<__half2*>(&u.x);
    __half2 b = *reinterpret_cast<__half2*>(&u.y);
    float2 fa = __half22float2(a), fb = __half22float2(b);
    return make_float4(fa.x, fa.y, fb.x, fb.y);
}

// ================= scratch =======================================================
__device__ float g_bufA[(size_t)NNODES * F];    // h1/h2 as fp16 (reused)
__device__ float g_bufB[(size_t)NNODES * F];    // R split: uint2[node*64+c]={hi,lo}
__device__ float g_dinv[NNODES];
__device__ int   g_deg[NNODES];
__device__ int   g_cursor[NNODES];
__device__ int   g_csr_ptr[NNODES + 1];
__device__ int   g_csr_src[NEDGES];
__device__ float g_csr_w[NEDGES];               // precomputed dinv[dst]*dinv[src]
__device__ int   g_blocksums[1024];
__device__ int   g_blockoff[1024];
__device__ float g_cell[(size_t)NG * F];
__device__ float g_sums[3 * 2 * F];
__device__ float g_const[F];
__device__ int   g_maxb[NG * F];
__device__ __nv_bfloat16 g_w1hi[F * F], g_w1lo[F * F], g_w2hi[F * F], g_w2lo[F * F];

// ================= init / degree / CSR ==========================================
__global__ void init_kernel() {
    int i = blockIdx.x * blockDim.x + threadIdx.x;
    if (i < NNODES) { g_deg[i] = 0; g_cursor[i] = 0; }
    if (i < 2 * 2 * F) g_sums[i] = 0.0f;
    for (int j = i; j < NG * F; j += gridDim.x * blockDim.x) g_maxb[j] = 0;
}
__global__ void zero_cell_sums() {
    g_sums[512 + threadIdx.x] = 0.0f;
}
__global__ void deg_kernel(const int* __restrict__ dst) {
    int e = blockIdx.x * blockDim.x + threadIdx.x;
    if (e < NEDGES) atomicAdd(&g_deg[dst[e]], 1);
}
__global__ void scan1_kernel() {
    __shared__ int sh[256];
    int i = blockIdx.x * 256 + threadIdx.x;
    int v = (i < NNODES) ? g_deg[i] : 0;
    if (i < NNODES) g_dinv[i] = rsqrtf((float)v + 1.0f);
    sh[threadIdx.x] = v;
    __syncthreads();
#pragma unroll
    for (int off = 1; off < 256; off <<= 1) {
        int t = (threadIdx.x >= off) ? sh[threadIdx.x - off] : 0;
        __syncthreads();
        sh[threadIdx.x] += t;
        __syncthreads();
    }
    if (i < NNODES) g_csr_ptr[i] = sh[threadIdx.x] - v;
    if (threadIdx.x == 255) g_blocksums[blockIdx.x] = sh[255];
}
__global__ void scan2_kernel() {
    __shared__ int sh[1024];
    int t = threadIdx.x;
    int v = (t < NBLK) ? g_blocksums[t] : 0;
    sh[t] = v;
    __syncthreads();
#pragma unroll
    for (int off = 1; off < 1024; off <<= 1) {
        int u = (t >= off) ? sh[t - off] : 0;
        __syncthreads();
        sh[t] += u;
        __syncthreads();
    }
    if (t < NBLK) g_blockoff[t] = sh[t] - v;
}
__global__ void scan3_kernel() {
    int i = blockIdx.x * blockDim.x + threadIdx.x;
    if (i < NNODES) g_csr_ptr[i] += g_blockoff[i >> 8];
    if (i == 0) g_csr_ptr[NNODES] = NEDGES;
}
// fill edge list AND precomputed norm weight (dinv ready after scan1)
__global__ void fill_kernel(const int* __restrict__ src, const int* __restrict__ dst) {
    int e = blockIdx.x * blockDim.x + threadIdx.x;
    if (e >= NEDGES) return;
    int d = dst[e];
    int s = src[e];
    int pos = g_csr_ptr[d] + atomicAdd(&g_cursor[d], 1);
    g_csr_src[pos] = s;
    g_csr_w[pos]   = g_dinv[d] * g_dinv[s];
}

// ================= weight prep ===================================================
__global__ void wprep1_kernel(const float* __restrict__ W1) {
    int i = blockIdx.x * blockDim.x + threadIdx.x;
    if (i >= F * F) return;
    int k = i >> 7, n = i & 127;
    float v = W1[i];
    __nv_bfloat16 h = __float2bfloat16(v);
    g_w1hi[n * F + k] = h;
    g_w1lo[n * F + k] = __float2bfloat16(v - __bfloat162float(h));
}

// fold BN1 into W2, affine computed inline from raw sums
__global__ void wprep2_kernel(const float* __restrict__ W2, const float* __restrict__ sums,
                              const float* __restrict__ g1, const float* __restrict__ be1) {
    __shared__ float red[128];
    int n = blockIdx.x, k = threadIdx.x;
    const float invM = 1.0f / (float)NNODES;
    float m   = sums[k] * invM;
    float var = sums[F + k] * invM - m * m;
    float sc  = g1[k] * rsqrtf(var + BN_EPS);
    float sh  = be1[k] - sc * m;
    float w   = W2[k * 128 + n];
    float ws  = w * sc;
    __nv_bfloat16 h = __float2bfloat16(ws);
    g_w2hi[n * 128 + k] = h;
    g_w2lo[n * 128 + k] = __float2bfloat16(ws - __bfloat162float(h));
    red[k] = sh * w;
    __syncthreads();
#pragma unroll
    for (int off = 64; off; off >>= 1) {
        if (k < off) red[k] += red[k + off];
        __syncthreads();
    }
    if (k == 0) g_const[n] = red[0];
}

// ================= GEMM-1: h1(fp16) = split3(x fp32) @ W1 (BM=128) ==============
#define AST    136
#define SW_HI  0
#define SW_LO  (128 * AST * 2)
#define MMA_SMEM (2 * 128 * AST * 2)   // 69632

__global__ void __launch_bounds__(256, 2)
gemm_mma(const float* __restrict__ A, int M,
         const __nv_bfloat16* __restrict__ Whi, const __nv_bfloat16* __restrict__ Wlo,
         __half* __restrict__ C)
{
    extern __shared__ char sm[];
    const int tid  = threadIdx.x;
    const int lane = tid & 31;
    const int wid  = tid >> 5;
    const int m0   = blockIdx.x * 128;

    for (int i = tid; i < 2048; i += 256) {
        int n = i >> 4, kg = i & 15;
        *(uint4*)(sm + SW_HI + ((size_t)n * AST + kg * 8) * 2) = *(const uint4*)(Whi + n * 128 + kg * 8);
        *(uint4*)(sm + SW_LO + ((size_t)n * AST + kg * 8) * 2) = *(const uint4*)(Wlo + n * 128 + kg * 8);
    }
    __syncthreads();

    const int wm = (wid & 3) * 32;
    const int wn = (wid >> 2) * 64;
    uint32_t sb  = smem_to_u32(sm);
    uint32_t brw = wn + (lane >> 4) * 8 + (lane & 7);
    uint32_t bHi = sb + SW_HI + ((brw * AST + ((lane >> 3) & 1) * 8) << 1);
    uint32_t bLo = bHi + SW_LO;

    const int r0 = lane >> 2;
    const int c0 = (lane & 3) * 2;
    const int rowA = m0 + wm + r0;
    const bool okA[2][2] = {{rowA < M, rowA + 8 < M}, {rowA + 16 < M, rowA + 24 < M}};

    float c[2][8][4];
#pragma unroll
    for (int f = 0; f < 2; f++)
#pragma unroll
        for (int j = 0; j < 8; j++)
#pragma unroll
            for (int e = 0; e < 4; e++) c[f][j][e] = 0.0f;

    const float2 Z2 = make_float2(0.f, 0.f);
    float2 raw[2][4];
    {
#pragma unroll
        for (int f = 0; f < 2; f++) {
            const float* p0 = A + (size_t)(rowA + f * 16) * 128 + c0;
            raw[f][0] = okA[f][0] ? *(const float2*)p0          : Z2;
            raw[f][1] = okA[f][1] ? *(const float2*)(p0 + 1024) : Z2;
            raw[f][2] = okA[f][0] ? *(const float2*)(p0 + 8)    : Z2;
            raw[f][3] = okA[f][1] ? *(const float2*)(p0 + 1032) : Z2;
        }
    }

    uint32_t ah[2][4], al[2][4];
    auto do_split = [&](float2 (&rw)[2][4]) {
#pragma unroll
        for (int f = 0; f < 2; f++) {
            splitpack(rw[f][0].x, rw[f][0].y, ah[f][0], al[f][0]);
            splitpack(rw[f][1].x, rw[f][1].y, ah[f][1], al[f][1]);
            splitpack(rw[f][2].x, rw[f][2].y, ah[f][2], al[f][2]);
            splitpack(rw[f][3].x, rw[f][3].y, ah[f][3], al[f][3]);
        }
    };
    do_split(raw);

#pragma unroll
    for (int ks = 0; ks < 8; ks++) {
        float2 rn[2][4];
        if (ks < 7) {
            const int kc = (ks + 1) * 16 + c0;
#pragma unroll
            for (int f = 0; f < 2; f++) {
                const float* p0 = A + (size_t)(rowA + f * 16) * 128 + kc;
                rn[f][0] = okA[f][0] ? *(const float2*)p0          : Z2;
                rn[f][1] = okA[f][1] ? *(const float2*)(p0 + 1024) : Z2;
                rn[f][2] = okA[f][0] ? *(const float2*)(p0 + 8)    : Z2;
                rn[f][3] = okA[f][1] ? *(const float2*)(p0 + 1032) : Z2;
            }
        }
#pragma unroll
        for (int p = 0; p < 4; p++) {
            uint32_t bh[4], bl[4];
            LDSM_X4(bh, bHi + ks * 32 + p * 16 * AST * 2);
            LDSM_X4(bl, bLo + ks * 32 + p * 16 * AST * 2);
#pragma unroll
            for (int f = 0; f < 2; f++)
#pragma unroll
                for (int q = 0; q < 2; q++) {
                    int j = p * 2 + q;
                    MMA16816(c[f][j], ah[f][0], ah[f][1], ah[f][2], ah[f][3], bh[q * 2], bh[q * 2 + 1]);
                    MMA16816(c[f][j], al[f][0], al[f][1], al[f][2], al[f][3], bh[q * 2], bh[q * 2 + 1]);
                    MMA16816(c[f][j], ah[f][0], ah[f][1], ah[f][2], ah[f][3], bl[q * 2], bl[q * 2 + 1]);
                }
        }
        if (ks < 7) do_split(rn);
    }

    const int cc = (lane & 3) * 2;
#pragma unroll
    for (int f = 0; f < 2; f++) {
        int row = m0 + wm + f * 16 + r0;
#pragma unroll
        for (int j = 0; j < 8; j++) {
            int col = wn + j * 8 + cc;
            if (row < M)
                *(__half2*)(C + (size_t)row * 128 + col) = __floats2half2_rn(c[f][j][0], c[f][j][1]);
            if (row + 8 < M)
                *(__half2*)(C + (size_t)(row + 8) * 128 + col) = __floats2half2_rn(c[f][j][2], c[f][j][3]);
        }
    }
}

// ================= GEMM-2 lite: h2(fp16) = (Rhi+Rlo) @ W2' + const (BM=128) =====
#define LCONST (2 * 128 * AST * 2)
#define LITE_SMEM (LCONST + 512)

__global__ void __launch_bounds__(256, 2)
gemm_lite(const uint2* __restrict__ Rq, int M,
          const __nv_bfloat16* __restrict__ Whi, const __nv_bfloat16* __restrict__ Wlo,
          const float* __restrict__ cst, __half* __restrict__ C)
{
    extern __shared__ char sm[];
    float* csm = (float*)(sm + LCONST);
    const int tid  = threadIdx.x;
    const int lane = tid & 31;
    const int wid  = tid >> 5;
    const int m0   = blockIdx.x * 128;

    for (int i = tid; i < 2048; i += 256) {
        int n = i >> 4, kg = i & 15;
        *(uint4*)(sm + SW_HI + ((size_t)n * AST + kg * 8) * 2) = *(const uint4*)(Whi + n * 128 + kg * 8);
        *(uint4*)(sm + SW_LO + ((size_t)n * AST + kg * 8) * 2) = *(const uint4*)(Wlo + n * 128 + kg * 8);
    }
    if (tid < 128) csm[tid] = cst[tid];
    __syncthreads();

    const int wm = (wid & 3) * 32;
    const int wn = (wid >> 2) * 64;
    uint32_t sb  = smem_to_u32(sm);
    uint32_t brw = wn + (lane >> 4) * 8 + (lane & 7);
    uint32_t bHi = sb + SW_HI + ((brw * AST + ((lane >> 3) & 1) * 8) << 1);
    uint32_t bLo = bHi + SW_LO;

    const int r0 = lane >> 2;
    const int q0 = lane & 3;
    const int rowA = m0 + wm + r0;
    const bool okA[2][2] = {{rowA < M, rowA + 8 < M}, {rowA + 16 < M, rowA + 24 < M}};

    float c[2][8][4];
#pragma unroll
    for (int f = 0; f < 2; f++)
#pragma unroll
        for (int j = 0; j < 8; j++)
#pragma unroll
            for (int e = 0; e < 4; e++) c[f][j][e] = 0.0f;

    const uint2 ZU = make_uint2(0u, 0u);
    auto loadA = [&](int ks, uint2 (&fr)[2][4]) {
        int cb = ks * 8 + q0;
#pragma unroll
        for (int f = 0; f < 2; f++) {
            const uint2* p = Rq + (size_t)(rowA + f * 16) * 64 + cb;
            fr[f][0] = okA[f][0] ? p[0]   : ZU;
            fr[f][1] = okA[f][1] ? p[512] : ZU;
            fr[f][2] = okA[f][0] ? p[4]   : ZU;
            fr[f][3] = okA[f][1] ? p[516] : ZU;
        }
    };

    uint2 cur[2][4], nxt[2][4];
    loadA(0, cur);

#pragma unroll
    for (int ks = 0; ks < 8; ks++) {
        if (ks < 7) loadA(ks + 1, nxt);
#pragma unroll
        for (int p = 0; p < 4; p++) {
            uint32_t bh[4], bl[4];
            LDSM_X4(bh, bHi + ks * 32 + p * 16 * AST * 2);
            LDSM_X4(bl, bLo + ks * 32 + p * 16 * AST * 2);
#pragma unroll
            for (int f = 0; f < 2; f++)
#pragma unroll
                for (int q = 0; q < 2; q++) {
                    int j = p * 2 + q;
                    MMA16816(c[f][j], cur[f][0].x, cur[f][1].x, cur[f][2].x, cur[f][3].x, bh[q * 2], bh[q * 2 + 1]);
                    MMA16816(c[f][j], cur[f][0].y, cur[f][1].y, cur[f][2].y, cur[f][3].y, bh[q * 2], bh[q * 2 + 1]);
                    MMA16816(c[f][j], cur[f][0].x, cur[f][1].x, cur[f][2].x, cur[f][3].x, bl[q * 2], bl[q * 2 + 1]);
                }
        }
        if (ks < 7) {
#pragma unroll
            for (int f = 0; f < 2; f++)
#pragma unroll
                for (int i = 0; i < 4; i++) cur[f][i] = nxt[f][i];
        }
    }

    const int cc = (lane & 3) * 2;
#pragma unroll
    for (int f = 0; f < 2; f++) {
        int row = m0 + wm + f * 16 + r0;
#pragma unroll
        for (int j = 0; j < 8; j++) {
            int col = wn + j * 8 + cc;
            float k0 = csm[col], k1 = csm[col + 1];
            if (row < M)
                *(__half2*)(C + (size_t)row * 128 + col) = __floats2half2_rn(c[f][j][0] + k0, c[f][j][1] + k1);
            if (row + 8 < M)
                *(__half2*)(C + (size_t)(row + 8) * 128 + col) = __floats2half2_rn(c[f][j][2] + k0, c[f][j][3] + k1);
        }
    }
}

// ================= gather core (CSR, fp16 rows, precomputed edge weights) ========
__device__ __forceinline__ float4 gather_acc(const __half* __restrict__ h, int node, int lane) {
    int beg = g_csr_ptr[node];
    int end = g_csr_ptr[node + 1];
    float di = g_dinv[node];
    const uint2* hv = (const uint2*)h;
    float4 acc = h4f(hv[(size_t)node * 32 + lane]);
    float sn = di * di;
    acc.x *= sn; acc.y *= sn; acc.z *= sn; acc.w *= sn;
    int e = beg;
    for (; e + 3 < end; e += 4) {
        int s0 = __ldg(&g_csr_src[e]);
        int s1 = __ldg(&g_csr_src[e + 1]);
        int s2 = __ldg(&g_csr_src[e + 2]);
        int s3 = __ldg(&g_csr_src[e + 3]);
        float n0 = __ldg(&g_csr_w[e]);
        float n1 = __ldg(&g_csr_w[e + 1]);
        float n2 = __ldg(&g_csr_w[e + 2]);
        float n3 = __ldg(&g_csr_w[e + 3]);
        float4 v0 = h4f(hv[(size_t)s0 * 32 + lane]);
        float4 v1 = h4f(hv[(size_t)s1 * 32 + lane]);
        float4 v2 = h4f(hv[(size_t)s2 * 32 + lane]);
        float4 v3 = h4f(hv[(size_t)s3 * 32 + lane]);
        acc.x = fmaf(v0.x, n0, acc.x); acc.y = fmaf(v0.y, n0, acc.y);
        acc.z = fmaf(v0.z, n0, acc.z); acc.w = fmaf(v0.w, n0, acc.w);
        acc.x = fmaf(v1.x, n1, acc.x); acc.y = fmaf(v1.y, n1, acc.y);
        acc.z = fmaf(v1.z, n1, acc.z); acc.w = fmaf(v1.w, n1, acc.w);
        acc.x = fmaf(v2.x, n2, acc.x); acc.y = fmaf(v2.y, n2, acc.y);
        acc.z = fmaf(v2.z, n2, acc.z); acc.w = fmaf(v2.w, n2, acc.w);
        acc.x = fmaf(v3.x, n3, acc.x); acc.y = fmaf(v3.y, n3, acc.y);
        acc.z = fmaf(v3.z, n3, acc.z); acc.w = fmaf(v3.w, n3, acc.w);
    }
    for (; e < end; e++) {
        int s0 = __ldg(&g_csr_src[e]);
        float n0 = __ldg(&g_csr_w[e]);
        float4 v0 = h4f(hv[(size_t)s0 * 32 + lane]);
        acc.x = fmaf(v0.x, n0, acc.x); acc.y = fmaf(v0.y, n0, acc.y);
        acc.z = fmaf(v0.z, n0, acc.z); acc.w = fmaf(v0.w, n0, acc.w);
    }
    return acc;
}

#define NPW 8   // nodes per warp

// gather-1: 256 threads = 8 warps = 64 nodes/block; natural regs (no cap) ->
// ~3 CTAs/SM = 24 warps resident. BN sums in registers (R12 logic unchanged).
__global__ void gather_split_kernel(const __half* __restrict__ h, uint4* __restrict__ Rq4,
                                    const float* __restrict__ bias, float* __restrict__ sums)
{
    __shared__ float ss[256];
    int tid = threadIdx.x;                    // 256 threads = 8 warps = 64 nodes
    ss[tid] = 0.0f;
    __syncthreads();

    int lane = tid & 31;
    int base = blockIdx.x * 64 + (tid >> 5) * NPW;
    int d = lane * 4;
    float4 b4 = make_float4(bias[d], bias[d + 1], bias[d + 2], bias[d + 3]);

    float s0 = 0, s1 = 0, s2 = 0, s3 = 0, q0 = 0, q1 = 0, q2 = 0, q3 = 0;
    for (int i = 0; i < NPW; i++) {
        int node = base + i;
        if (node >= NNODES) break;
        float4 acc = gather_acc(h, node, lane);
        float v0 = fmaxf(acc.x + b4.x, 0.0f);
        float v1 = fmaxf(acc.y + b4.y, 0.0f);
        float v2 = fmaxf(acc.z + b4.z, 0.0f);
        float v3 = fmaxf(acc.w + b4.w, 0.0f);
        uint32_t h01, l01, h23, l23;
        splitpack(v0, v1, h01, l01);
        splitpack(v2, v3, h23, l23);
        Rq4[(size_t)node * 32 + lane] = make_uint4(h01, l01, h23, l23);
        s0 += v0; q0 += v0 * v0;
        s1 += v1; q1 += v1 * v1;
        s2 += v2; q2 += v2 * v2;
        s3 += v3; q3 += v3 * v3;
    }
    atomicAdd(&ss[d + 0], s0);  atomicAdd(&ss[128 + d + 0], q0);
    atomicAdd(&ss[d + 1], s1);  atomicAdd(&ss[128 + d + 1], q1);
    atomicAdd(&ss[d + 2], s2);  atomicAdd(&ss[128 + d + 2], q2);
    atomicAdd(&ss[d + 3], s3);  atomicAdd(&ss[128 + d + 3], q3);
    __syncthreads();
    atomicAdd(&sums[tid], ss[tid]);
}

// gather-2: register BN sums + register pool-max flushed on graph transitions
__global__ void gather_pool_kernel(const __half* __restrict__ h, const int* __restrict__ ibatch,
                                   const float* __restrict__ bias, float* __restrict__ sums)
{
    __shared__ float ss[256];
    int tid = threadIdx.x;                    // 256 threads = 8 warps = 64 nodes
    ss[tid] = 0.0f;
    __syncthreads();

    int lane = tid & 31;
    int base = blockIdx.x * 64 + (tid >> 5) * NPW;
    int d = lane * 4;
    float4 b4 = make_float4(bias[d], bias[d + 1], bias[d + 2], bias[d + 3]);

    float s0 = 0, s1 = 0, s2 = 0, s3 = 0, q0 = 0, q1 = 0, q2 = 0, q3 = 0;
    float m0 = 0, m1 = 0, m2 = 0, m3 = 0;
    int cur_g = -1;

    for (int i = 0; i < NPW; i++) {
        int node = base + i;
        if (node >= NNODES) break;
        int g = 0;
        if (lane == 0) g = __ldg(&ibatch[node]);
        g = __shfl_sync(0xffffffffu, g, 0);
        if (g != cur_g) {
            if (cur_g >= 0) {
                int* mb = g_maxb + cur_g * F + d;
                atomicMax(mb + 0, __float_as_int(m0));
                atomicMax(mb + 1, __float_as_int(m1));
                atomicMax(mb + 2, __float_as_int(m2));
                atomicMax(mb + 3, __float_as_int(m3));
            }
            cur_g = g;
            m0 = m1 = m2 = m3 = 0.0f;   // values are relu >= 0
        }
        float4 acc = gather_acc(h, node, lane);
        float v0 = fmaxf(acc.x + b4.x, 0.0f);
        float v1 = fmaxf(acc.y + b4.y, 0.0f);
        float v2 = fmaxf(acc.z + b4.z, 0.0f);
        float v3 = fmaxf(acc.w + b4.w, 0.0f);
        m0 = fmaxf(m0, v0); m1 = fmaxf(m1, v1);
        m2 = fmaxf(m2, v2); m3 = fmaxf(m3, v3);
        s0 += v0; q0 += v0 * v0;
        s1 += v1; q1 += v1 * v1;
        s2 += v2; q2 += v2 * v2;
        s3 += v3; q3 += v3 * v3;
    }
    if (cur_g >= 0) {
        int* mb = g_maxb + cur_g * F + d;
        atomicMax(mb + 0, __float_as_int(m0));
        atomicMax(mb + 1, __float_as_int(m1));
        atomicMax(mb + 2, __float_as_int(m2));
        atomicMax(mb + 3, __float_as_int(m3));
    }
    atomicAdd(&ss[d + 0], s0);  atomicAdd(&ss[128 + d + 0], q0);
    atomicAdd(&ss[d + 1], s1);  atomicAdd(&ss[128 + d + 1], q1);
    atomicAdd(&ss[d + 2], s2);  atomicAdd(&ss[128 + d + 2], q2);
    atomicAdd(&ss[d + 3], s3);  atomicAdd(&ss[128 + d + 3], q3);
    __syncthreads();
    atomicAdd(&sums[tid], ss[tid]);
}

// out = BN2(max) with affine computed inline from raw sums
__global__ void pool_out_kernel(const float* __restrict__ sums2, const float* __restrict__ g2,
                                const float* __restrict__ be2, float* __restrict__ out)
{
    int idx = blockIdx.x * blockDim.x + threadIdx.x;
    if (idx >= NG * F) return;
    int d = idx & 127;
    const float invM = 1.0f / (float)NNODES;
    float m   = sums2[d] * invM;
    float var = sums2[F + d] * invM - m * m;
    float sc  = g2[d] * rsqrtf(var + BN_EPS);
    float v   = __int_as_float(g_maxb[idx]);
    out[idx]  = fmaf(sc, v, be2[d] - sc * m);
}

// ================= cell branch helpers ==========================================
__global__ void bn_stats_kernel(const float* __restrict__ in, float* __restrict__ sums, int M) {
    int d = threadIdx.x;
    float s = 0.0f, q = 0.0f;
    for (int r = blockIdx.x; r < M; r += gridDim.x) {
        float v = in[(size_t)r * F + d];
        s += v; q += v * v;
    }
    atomicAdd(&sums[d], s);
    atomicAdd(&sums[F + d], q);
}

__global__ void bn_apply_kernel(const float* __restrict__ in, const float* __restrict__ sums,
                                const float* __restrict__ gamma, const float* __restrict__ beta,
                                float* __restrict__ out, int M)
{
    int i = blockIdx.x * blockDim.x + threadIdx.x;
    if (i >= M * F) return;
    int d = i & 127;
    float invM = 1.0f / (float)M;
    float m   = sums[d] * invM;
    float var = sums[F + d] * invM - m * m;
    out[i] = gamma[d] * (in[i] - m) * rsqrtf(var + BN_EPS) + beta[d];
}

__global__ __launch_bounds__(256) void gemm128(
    const float* __restrict__ A, const float* __restrict__ B,
    const float* __restrict__ bias, float* __restrict__ C,
    int M, int K, int act)
{
    __shared__ float As[16][132];
    __shared__ float Bs[16][128];
    const int tid = threadIdx.x;
    const int m0  = blockIdx.x * 128;
    const int tn  = tid & 15;
    const int tm  = tid >> 4;
    float acc[8][8];
#pragma unroll
    for (int i = 0; i < 8; i++)
#pragma unroll
        for (int j = 0; j < 8; j++) acc[i][j] = 0.0f;
    const int arow = tid >> 4, acol = tid & 15;
    const int brow = tid >> 7, bcol = tid & 127;
    for (int kk = 0; kk < K; kk += 16) {
#pragma unroll
        for (int p = 0; p < 8; p++) {
            int m = p * 16 + arow, gk = kk + acol, gm = m0 + m;
            float v = 0.0f;
            if (gm < M && gk < K) v = A[(size_t)gm * K + gk];
            As[acol][m] = v;
        }
#pragma unroll
        for (int q = 0; q < 8; q++) {
            int k = q * 2 + brow, gk = kk + k;
            Bs[k][bcol] = (gk < K) ? B[(size_t)gk * 128 + bcol] : 0.0f;
        }
        __syncthreads();
#pragma unroll
        for (int k = 0; k < 16; k++) {
            float4 a0 = *(const float4*)&As[k][tm * 8];
            float4 a1 = *(const float4*)&As[k][tm * 8 + 4];
            float4 b0 = *(const float4*)&Bs[k][tn * 8];
            float4 b1 = *(const float4*)&Bs[k][tn * 8 + 4];
            float a[8] = {a0.x, a0.y, a0.z, a0.w, a1.x, a1.y, a1.z, a1.w};
            float b[8] = {b0.x, b0.y, b0.z, b0.w, b1.x, b1.y, b1.z, b1.w};
#pragma unroll
            for (int i = 0; i < 8; i++)
#pragma unroll
                for (int j = 0; j < 8; j++)
                    acc[i][j] = fmaf(a[i], b[j], acc[i][j]);
        }
        __syncthreads();
    }
#pragma unroll
    for (int i = 0; i < 8; i++) {
        int gm = m0 + tm * 8 + i;
        if (gm >= M) continue;
        float o[8];
#pragma unroll
        for (int j = 0; j < 8; j++) {
            float v = acc[i][j] + bias[tn * 8 + j];
            if (act == 1)      v = fmaxf(v, 0.0f);
            else if (act == 2) v = tanhf(v);
            o[j] = v;
        }
        float4* cp = (float4*)&C[(size_t)gm * 128 + tn * 8];
        cp[0] = make_float4(o[0], o[1], o[2], o[3]);
        cp[1] = make_float4(o[4], o[5], o[6], o[7]);
    }
}

// ================= launch ========================================================
extern "C" void kernel_launch(void* const* d_in, const int* in_sizes, int n_in,
                              void* d_out, int out_size)
{
    const float* x      = (const float*)d_in[0];
    const int*   eidx   = (const int*)  d_in[1];
    const int*   ibatch = (const int*)  d_in[2];
    const float* gexpr  = (const float*)d_in[3];
    const float* W1  = (const float*)d_in[4];
    const float* b1  = (const float*)d_in[5];
    const float* g1  = (const float*)d_in[6];
    const float* be1 = (const float*)d_in[7];
    const float* W2  = (const float*)d_in[8];
    const float* b2  = (const float*)d_in[9];
    const float* g2  = (const float*)d_in[10];
    const float* be2 = (const float*)d_in[11];
    const float* Wc1 = (const float*)d_in[12];
    const float* bc1 = (const float*)d_in[13];
    const float* gc  = (const float*)d_in[14];
    const float* bec = (const float*)d_in[15];
    const float* Wc2 = (const float*)d_in[16];
    const float* bc2 = (const float*)d_in[17];
    float* out = (float*)d_out;

    const int* src = eidx;
    const int* dst = eidx + NEDGES;

    float* bufA; cudaGetSymbolAddress((void**)&bufA, g_bufA);
    float* bufB; cudaGetSymbolAddress((void**)&bufB, g_bufB);
    float* cell; cudaGetSymbolAddress((void**)&cell, g_cell);
    float* sums; cudaGetSymbolAddress((void**)&sums, g_sums);
    float* cst;  cudaGetSymbolAddress((void**)&cst,  g_const);
    __nv_bfloat16 *w1hi, *w1lo, *w2hi, *w2lo;
    cudaGetSymbolAddress((void**)&w1hi, g_w1hi);
    cudaGetSymbolAddress((void**)&w1lo, g_w1lo);
    cudaGetSymbolAddress((void**)&w2hi, g_w2hi);
    cudaGetSymbolAddress((void**)&w2lo, g_w2lo);
    __half* hbuf = (__half*)bufA;

    cudaFuncSetAttribute(gemm_mma,  cudaFuncAttributeMaxDynamicSharedMemorySize, MMA_SMEM);
    cudaFuncSetAttribute(gemm_lite, cudaFuncAttributeMaxDynamicSharedMemorySize, LITE_SMEM);

    static cudaStream_t s_csr = nullptr, s_cell = nullptr;
    static cudaEvent_t ev_root = nullptr, ev_csr = nullptr, ev_cell = nullptr;
    if (!s_csr) {
        cudaStreamCreateWithFlags(&s_csr,  cudaStreamNonBlocking);
        cudaStreamCreateWithFlags(&s_cell, cudaStreamNonBlocking);
        cudaEventCreateWithFlags(&ev_root, cudaEventDisableTiming);
        cudaEventCreateWithFlags(&ev_csr,  cudaEventDisableTiming);
        cudaEventCreateWithFlags(&ev_cell, cudaEventDisableTiming);
    }

    const int T = 256;
    int gN  = (NNODES + T - 1) / T;
    int gE  = (NEDGES + T - 1) / T;
    int gGF = (NG * F + T - 1) / T;
    int gGather = (NNODES + 63) / 64;     // 3125 blocks x 8 warps x 8 nodes
    int gTile   = (NNODES + 127) / 128;   // 1563
    int gGemmG  = (NG + 127) / 128;

    // ---- fork
    cudaEventRecord(ev_root, 0);
    cudaStreamWaitEvent(s_csr,  ev_root, 0);
    cudaStreamWaitEvent(s_cell, ev_root, 0);

    // submissions 1-4 (gemm_mma stays in ncu slot)
    init_kernel<<<gN, T, 0, s_csr>>>();
    deg_kernel<<<gE, T, 0, s_csr>>>(dst);
    wprep1_kernel<<<(F * F + 255) / 256, 256>>>(W1);
    gemm_mma<<<gTile, 256, MMA_SMEM>>>(x, NNODES, w1hi, w1lo, hbuf);

    // ---- rest of CSR branch
    scan1_kernel<<<NBLK, 256, 0, s_csr>>>();
    scan2_kernel<<<1, 1024, 0, s_csr>>>();
    scan3_kernel<<<gN, T, 0, s_csr>>>();
    fill_kernel<<<gE, T, 0, s_csr>>>(src, dst);
    cudaEventRecord(ev_csr, s_csr);

    // ---- cell branch
    zero_cell_sums<<<1, 256, 0, s_cell>>>();
    gemm128<<<gGemmG, 256, 0, s_cell>>>(gexpr, Wc1, bc1, cell, NG, DCELL, 2);
    bn_stats_kernel<<<512, 128, 0, s_cell>>>(cell, sums + 512, NG);
    bn_apply_kernel<<<gGF, T, 0, s_cell>>>(cell, sums + 512, gc, bec, cell, NG);
    gemm128<<<gGemmG, 256, 0, s_cell>>>(cell, Wc2, bc2, out + (size_t)NG * F, NG, 128, 1);
    cudaEventRecord(ev_cell, s_cell);

    // ---- main: join CSR, aggregation pipeline
    cudaStreamWaitEvent(0, ev_csr, 0);
    gather_split_kernel<<<gGather, 256>>>(hbuf, (uint4*)bufB, b1, sums + 0);
    wprep2_kernel<<<128, 128>>>(W2, sums + 0, g1, be1);

    gemm_lite<<<gTile, 256, LITE_SMEM>>>((const uint2*)bufB, NNODES, w2hi, w2lo, cst, hbuf);
    gather_pool_kernel<<<gGather, 256>>>(hbuf, ibatch, b2, sums + 256);
    pool_out_kernel<<<gGF, T>>>(sums + 256, g2, be2, out);

    // ---- join cell branch
    cudaStreamWaitEvent(0, ev_cell, 0);
}

// round 17
// speedup vs baseline: 1.2454x; 1.0124x over previous
#include <cuda_runtime.h>
#include <cuda_bf16.h>
#include <cuda_fp16.h>
#include <math.h>
#include <cstdint>

#define NNODES 200000
#define NEDGES 800000
#define NG     4096
#define DCELL  954
#define F      128
#define BN_EPS 1e-5f
#define NBLK   782          // ceil(NNODES/256)

// ================= mma.sync helpers =============================================
__device__ __forceinline__ uint32_t smem_to_u32(const void* p) {
    uint32_t a;
    asm("{ .reg .u64 t; cvta.to.shared.u64 t, %1; cvt.u32.u64 %0, t; }" : "=r"(a) : "l"(p));
    return a;
}

#define LDSM_X4(r, addr) \
    asm volatile("ldmatrix.sync.aligned.m8n8.x4.shared.b16 {%0,%1,%2,%3}, [%4];" \
        : "=r"((r)[0]), "=r"((r)[1]), "=r"((r)[2]), "=r"((r)[3]) : "r"(addr))

#define MMA16816(c, a0, a1, a2, a3, b0, b1) \
    asm volatile("mma.sync.aligned.m16n8k16.row.col.f32.bf16.bf16.f32 " \
        "{%0,%1,%2,%3}, {%4,%5,%6,%7}, {%8,%9}, {%0,%1,%2,%3};" \
        : "+f"((c)[0]), "+f"((c)[1]), "+f"((c)[2]), "+f"((c)[3]) \
        : "r"(a0), "r"(a1), "r"(a2), "r"(a3), "r"(b0), "r"(b1))

__device__ __forceinline__ void splitpack(float x, float y, uint32_t& hi, uint32_t& lo) {
    __nv_bfloat16 hx = __float2bfloat16(x), hy = __float2bfloat16(y);
    __nv_bfloat162 h2 = __halves2bfloat162(hx, hy);
    hi = *reinterpret_cast<uint32_t*>(&h2);
    __nv_bfloat162 l2 = __halves2bfloat162(__float2bfloat16(x - __bfloat162float(hx)),
                                           __float2bfloat16(y - __bfloat162float(hy)));
    lo = *reinterpret_cast<uint32_t*>(&l2);
}

__device__ __forceinline__ float4 h4f(uint2 u) {
    __half2 a = *reinterpret_cast<__half2*>(&u.x);
    __half2 b = *reinterpret_cast<__half2*>(&u.y);
    float2 fa = __half22float2(a), fb = __half22float2(b);
    return make_float4(fa.x, fa.y, fb.x, fb.y);
}

// ================= scratch =======================================================
__device__ float g_bufA[(size_t)NNODES * F];    // h1/h2 as fp16 (reused)
__device__ float g_bufB[(size_t)NNODES * F];    // R split: uint2[node*64+c]={hi,lo}
__device__ float g_dinv[NNODES];
__device__ int   g_deg[NNODES];
__device__ int   g_cursor[NNODES];
__device__ int   g_csr_ptr[NNODES + 1];
__device__ int   g_csr_src[NEDGES];
__device__ float g_csr_w[NEDGES];               // precomputed dinv[dst]*dinv[src]
__device__ int   g_blocksums[1024];
__device__ int   g_blockoff[1024];
__device__ float g_cell[(size_t)NG * F];
__device__ float g_sums[3 * 2 * F];
__device__ float g_const[F];
__device__ int   g_maxb[NG * F];
__device__ __nv_bfloat16 g_w1hi[F * F], g_w1lo[F * F], g_w2hi[F * F], g_w2lo[F * F];

// ================= init / degree / CSR ==========================================
__global__ void init_kernel() {
    int i = blockIdx.x * blockDim.x + threadIdx.x;
    if (i < NNODES) { g_deg[i] = 0; g_cursor[i] = 0; }
    if (i < 2 * 2 * F) g_sums[i] = 0.0f;
    for (int j = i; j < NG * F; j += gridDim.x * blockDim.x) g_maxb[j] = 0;
}
__global__ void zero_cell_sums() {
    g_sums[512 + threadIdx.x] = 0.0f;
}
__global__ void deg_kernel(const int* __restrict__ dst) {
    int e = blockIdx.x * blockDim.x + threadIdx.x;
    if (e < NEDGES) atomicAdd(&g_deg[dst[e]], 1);
}
__global__ void scan1_kernel() {
    __shared__ int sh[256];
    int i = blockIdx.x * 256 + threadIdx.x;
    int v = (i < NNODES) ? g_deg[i] : 0;
    if (i < NNODES) g_dinv[i] = rsqrtf((float)v + 1.0f);
    sh[threadIdx.x] = v;
    __syncthreads();
#pragma unroll
    for (int off = 1; off < 256; off <<= 1) {
        int t = (threadIdx.x >= off) ? sh[threadIdx.x - off] : 0;
        __syncthreads();
        sh[threadIdx.x] += t;
        __syncthreads();
    }
    if (i < NNODES) g_csr_ptr[i] = sh[threadIdx.x] - v;
    if (threadIdx.x == 255) g_blocksums[blockIdx.x] = sh[255];
}
__global__ void scan2_kernel() {
    __shared__ int sh[1024];
    int t = threadIdx.x;
    int v = (t < NBLK) ? g_blocksums[t] : 0;
    sh[t] = v;
    __syncthreads();
#pragma unroll
    for (int off = 1; off < 1024; off <<= 1) {
        int u = (t >= off) ? sh[t - off] : 0;
        __syncthreads();
        sh[t] += u;
        __syncthreads();
    }
    if (t < NBLK) g_blockoff[t] = sh[t] - v;
}
__global__ void scan3_kernel() {
    int i = blockIdx.x * blockDim.x + threadIdx.x;
    if (i < NNODES) g_csr_ptr[i] += g_blockoff[i >> 8];
    if (i == 0) g_csr_ptr[NNODES] = NEDGES;
}
// fill edge list AND precomputed norm weight (dinv ready after scan1)
__global__ void fill_kernel(const int* __restrict__ src, const int* __restrict__ dst) {
    int e = blockIdx.x * blockDim.x + threadIdx.x;
    if (e >= NEDGES) return;
    int d = dst[e];
    int s = src[e];
    int pos = g_csr_ptr[d] + atomicAdd(&g_cursor[d], 1);
    g_csr_src[pos] = s;
    g_csr_w[pos]   = g_dinv[d] * g_dinv[s];
}

// ================= weight prep ===================================================
__global__ void wprep1_kernel(const float* __restrict__ W1) {
    int i = blockIdx.x * blockDim.x + threadIdx.x;
    if (i >= F * F) return;
    int k = i >> 7, n = i & 127;
    float v = W1[i];
    __nv_bfloat16 h = __float2bfloat16(v);
    g_w1hi[n * F + k] = h;
    g_w1lo[n * F + k] = __float2bfloat16(v - __bfloat162float(h));
}

// fold BN1 into W2, affine computed inline from raw sums
__global__ void wprep2_kernel(const float* __restrict__ W2, const float* __restrict__ sums,
                              const float* __restrict__ g1, const float* __restrict__ be1) {
    __shared__ float red[128];
    int n = blockIdx.x, k = threadIdx.x;
    const float invM = 1.0f / (float)NNODES;
    float m   = sums[k] * invM;
    float var = sums[F + k] * invM - m * m;
    float sc  = g1[k] * rsqrtf(var + BN_EPS);
    float sh  = be1[k] - sc * m;
    float w   = W2[k * 128 + n];
    float ws  = w * sc;
    __nv_bfloat16 h = __float2bfloat16(ws);
    g_w2hi[n * 128 + k] = h;
    g_w2lo[n * 128 + k] = __float2bfloat16(ws - __bfloat162float(h));
    red[k] = sh * w;
    __syncthreads();
#pragma unroll
    for (int off = 64; off; off >>= 1) {
        if (k < off) red[k] += red[k + off];
        __syncthreads();
    }
    if (k == 0) g_const[n] = red[0];
}

// ================= GEMM-1: h1(fp16) = split3(x fp32) @ W1 (BM=128) ==============
#define AST    136
#define SW_HI  0
#define SW_LO  (128 * AST * 2)
#define MMA_SMEM (2 * 128 * AST * 2)   // 69632

__global__ void __launch_bounds__(256, 2)
gemm_mma(const float* __restrict__ A, int M,
         const __nv_bfloat16* __restrict__ Whi, const __nv_bfloat16* __restrict__ Wlo,
         __half* __restrict__ C)
{
    extern __shared__ char sm[];
    const int tid  = threadIdx.x;
    const int lane = tid & 31;
    const int wid  = tid >> 5;
    const int m0   = blockIdx.x * 128;

    for (int i = tid; i < 2048; i += 256) {
        int n = i >> 4, kg = i & 15;
        *(uint4*)(sm + SW_HI + ((size_t)n * AST + kg * 8) * 2) = *(const uint4*)(Whi + n * 128 + kg * 8);
        *(uint4*)(sm + SW_LO + ((size_t)n * AST + kg * 8) * 2) = *(const uint4*)(Wlo + n * 128 + kg * 8);
    }
    __syncthreads();

    const int wm = (wid & 3) * 32;
    const int wn = (wid >> 2) * 64;
    uint32_t sb  = smem_to_u32(sm);
    uint32_t brw = wn + (lane >> 4) * 8 + (lane & 7);
    uint32_t bHi = sb + SW_HI + ((brw * AST + ((lane >> 3) & 1) * 8) << 1);
    uint32_t bLo = bHi + SW_LO;

    const int r0 = lane >> 2;
    const int c0 = (lane & 3) * 2;
    const int rowA = m0 + wm + r0;
    const bool okA[2][2] = {{rowA < M, rowA + 8 < M}, {rowA + 16 < M, rowA + 24 < M}};

    float c[2][8][4];
#pragma unroll
    for (int f = 0; f < 2; f++)
#pragma unroll
        for (int j = 0; j < 8; j++)
#pragma unroll
            for (int e = 0; e < 4; e++) c[f][j][e] = 0.0f;

    const float2 Z2 = make_float2(0.f, 0.f);
    float2 raw[2][4];
    {
#pragma unroll
        for (int f = 0; f < 2; f++) {
            const float* p0 = A + (size_t)(rowA + f * 16) * 128 + c0;
            raw[f][0] = okA[f][0] ? *(const float2*)p0          : Z2;
            raw[f][1] = okA[f][1] ? *(const float2*)(p0 + 1024) : Z2;
            raw[f][2] = okA[f][0] ? *(const float2*)(p0 + 8)    : Z2;
            raw[f][3] = okA[f][1] ? *(const float2*)(p0 + 1032) : Z2;
        }
    }

    uint32_t ah[2][4], al[2][4];
    auto do_split = [&](float2 (&rw)[2][4]) {
#pragma unroll
        for (int f = 0; f < 2; f++) {
            splitpack(rw[f][0].x, rw[f][0].y, ah[f][0], al[f][0]);
            splitpack(rw[f][1].x, rw[f][1].y, ah[f][1], al[f][1]);
            splitpack(rw[f][2].x, rw[f][2].y, ah[f][2], al[f][2]);
            splitpack(rw[f][3].x, rw[f][3].y, ah[f][3], al[f][3]);
        }
    };
    do_split(raw);

#pragma unroll
    for (int ks = 0; ks < 8; ks++) {
        float2 rn[2][4];
        if (ks < 7) {
            const int kc = (ks + 1) * 16 + c0;
#pragma unroll
            for (int f = 0; f < 2; f++) {
                const float* p0 = A + (size_t)(rowA + f * 16) * 128 + kc;
                rn[f][0] = okA[f][0] ? *(const float2*)p0          : Z2;
                rn[f][1] = okA[f][1] ? *(const float2*)(p0 + 1024) : Z2;
                rn[f][2] = okA[f][0] ? *(const float2*)(p0 + 8)    : Z2;
                rn[f][3] = okA[f][1] ? *(const float2*)(p0 + 1032) : Z2;
            }
        }
#pragma unroll
        for (int p = 0; p < 4; p++) {
            uint32_t bh[4], bl[4];
            LDSM_X4(bh, bHi + ks * 32 + p * 16 * AST * 2);
            LDSM_X4(bl, bLo + ks * 32 + p * 16 * AST * 2);
#pragma unroll
            for (int f = 0; f < 2; f++)
#pragma unroll
                for (int q = 0; q < 2; q++) {
                    int j = p * 2 + q;
                    MMA16816(c[f][j], ah[f][0], ah[f][1], ah[f][2], ah[f][3], bh[q * 2], bh[q * 2 + 1]);
                    MMA16816(c[f][j], al[f][0], al[f][1], al[f][2], al[f][3], bh[q * 2], bh[q * 2 + 1]);
                    MMA16816(c[f][j], ah[f][0], ah[f][1], ah[f][2], ah[f][3], bl[q * 2], bl[q * 2 + 1]);
                }
        }
        if (ks < 7) do_split(rn);
    }

    const int cc = (lane & 3) * 2;
#pragma unroll
    for (int f = 0; f < 2; f++) {
        int row = m0 + wm + f * 16 + r0;
#pragma unroll
        for (int j = 0; j < 8; j++) {
            int col = wn + j * 8 + cc;
            if (row < M)
                *(__half2*)(C + (size_t)row * 128 + col) = __floats2half2_rn(c[f][j][0], c[f][j][1]);
            if (row + 8 < M)
                *(__half2*)(C + (size_t)(row + 8) * 128 + col) = __floats2half2_rn(c[f][j][2], c[f][j][3]);
        }
    }
}

// ================= GEMM-2 lite: h2(fp16) = (Rhi+Rlo) @ W2' + const (BM=128) =====
#define LCONST (2 * 128 * AST * 2)
#define LITE_SMEM (LCONST + 512)

__global__ void __launch_bounds__(256, 2)
gemm_lite(const uint2* __restrict__ Rq, int M,
          const __nv_bfloat16* __restrict__ Whi, const __nv_bfloat16* __restrict__ Wlo,
          const float* __restrict__ cst, __half* __restrict__ C)
{
    extern __shared__ char sm[];
    float* csm = (float*)(sm + LCONST);
    const int tid  = threadIdx.x;
    const int lane = tid & 31;
    const int wid  = tid >> 5;
    const int m0   = blockIdx.x * 128;

    for (int i = tid; i < 2048; i += 256) {
        int n = i >> 4, kg = i & 15;
        *(uint4*)(sm + SW_HI + ((size_t)n * AST + kg * 8) * 2) = *(const uint4*)(Whi + n * 128 + kg * 8);
        *(uint4*)(sm + SW_LO + ((size_t)n * AST + kg * 8) * 2) = *(const uint4*)(Wlo + n * 128 + kg * 8);
    }
    if (tid < 128) csm[tid] = cst[tid];
    __syncthreads();

    const int wm = (wid & 3) * 32;
    const int wn = (wid >> 2) * 64;
    uint32_t sb  = smem_to_u32(sm);
    uint32_t brw = wn + (lane >> 4) * 8 + (lane & 7);
    uint32_t bHi = sb + SW_HI + ((brw * AST + ((lane >> 3) & 1) * 8) << 1);
    uint32_t bLo = bHi + SW_LO;

    const int r0 = lane >> 2;
    const int q0 = lane & 3;
    const int rowA = m0 + wm + r0;
    const bool okA[2][2] = {{rowA < M, rowA + 8 < M}, {rowA + 16 < M, rowA + 24 < M}};

    float c[2][8][4];
#pragma unroll
    for (int f = 0; f < 2; f++)
#pragma unroll
        for (int j = 0; j < 8; j++)
#pragma unroll
            for (int e = 0; e < 4; e++) c[f][j][e] = 0.0f;

    const uint2 ZU = make_uint2(0u, 0u);
    auto loadA = [&](int ks, uint2 (&fr)[2][4]) {
        int cb = ks * 8 + q0;
#pragma unroll
        for (int f = 0; f < 2; f++) {
            const uint2* p = Rq + (size_t)(rowA + f * 16) * 64 + cb;
            fr[f][0] = okA[f][0] ? p[0]   : ZU;
            fr[f][1] = okA[f][1] ? p[512] : ZU;
            fr[f][2] = okA[f][0] ? p[4]   : ZU;
            fr[f][3] = okA[f][1] ? p[516] : ZU;
        }
    };

    uint2 cur[2][4], nxt[2][4];
    loadA(0, cur);

#pragma unroll
    for (int ks = 0; ks < 8; ks++) {
        if (ks < 7) loadA(ks + 1, nxt);
#pragma unroll
        for (int p = 0; p < 4; p++) {
            uint32_t bh[4], bl[4];
            LDSM_X4(bh, bHi + ks * 32 + p * 16 * AST * 2);
            LDSM_X4(bl, bLo + ks * 32 + p * 16 * AST * 2);
#pragma unroll
            for (int f = 0; f < 2; f++)
#pragma unroll
                for (int q = 0; q < 2; q++) {
                    int j = p * 2 + q;
                    MMA16816(c[f][j], cur[f][0].x, cur[f][1].x, cur[f][2].x, cur[f][3].x, bh[q * 2], bh[q * 2 + 1]);
                    MMA16816(c[f][j], cur[f][0].y, cur[f][1].y, cur[f][2].y, cur[f][3].y, bh[q * 2], bh[q * 2 + 1]);
                    MMA16816(c[f][j], cur[f][0].x, cur[f][1].x, cur[f][2].x, cur[f][3].x, bl[q * 2], bl[q * 2 + 1]);
                }
        }
        if (ks < 7) {
#pragma unroll
            for (int f = 0; f < 2; f++)
#pragma unroll
                for (int i = 0; i < 4; i++) cur[f][i] = nxt[f][i];
        }
    }

    const int cc = (lane & 3) * 2;
#pragma unroll
    for (int f = 0; f < 2; f++) {
        int row = m0 + wm + f * 16 + r0;
#pragma unroll
        for (int j = 0; j < 8; j++) {
            int col = wn + j * 8 + cc;
            float k0 = csm[col], k1 = csm[col + 1];
            if (row < M)
                *(__half2*)(C + (size_t)row * 128 + col) = __floats2half2_rn(c[f][j][0] + k0, c[f][j][1] + k1);
            if (row + 8 < M)
                *(__half2*)(C + (size_t)(row + 8) * 128 + col) = __floats2half2_rn(c[f][j][2] + k0, c[f][j][3] + k1);
        }
    }
}

// ================= gather edge accumulation (given preloaded header) ============
__device__ __forceinline__ void gather_edges(const uint2* __restrict__ hv, int beg, int end,
                                             int lane, float4& acc)
{
    int e = beg;
    for (; e + 3 < end; e += 4) {
        int s0 = __ldg(&g_csr_src[e]);
        int s1 = __ldg(&g_csr_src[e + 1]);
        int s2 = __ldg(&g_csr_src[e + 2]);
        int s3 = __ldg(&g_csr_src[e + 3]);
        float n0 = __ldg(&g_csr_w[e]);
        float n1 = __ldg(&g_csr_w[e + 1]);
        float n2 = __ldg(&g_csr_w[e + 2]);
        float n3 = __ldg(&g_csr_w[e + 3]);
        float4 v0 = h4f(hv[(size_t)s0 * 32 + lane]);
        float4 v1 = h4f(hv[(size_t)s1 * 32 + lane]);
        float4 v2 = h4f(hv[(size_t)s2 * 32 + lane]);
        float4 v3 = h4f(hv[(size_t)s3 * 32 + lane]);
        acc.x = fmaf(v0.x, n0, acc.x); acc.y = fmaf(v0.y, n0, acc.y);
        acc.z = fmaf(v0.z, n0, acc.z); acc.w = fmaf(v0.w, n0, acc.w);
        acc.x = fmaf(v1.x, n1, acc.x); acc.y = fmaf(v1.y, n1, acc.y);
        acc.z = fmaf(v1.z, n1, acc.z); acc.w = fmaf(v1.w, n1, acc.w);
        acc.x = fmaf(v2.x, n2, acc.x); acc.y = fmaf(v2.y, n2, acc.y);
        acc.z = fmaf(v2.z, n2, acc.z); acc.w = fmaf(v2.w, n2, acc.w);
        acc.x = fmaf(v3.x, n3, acc.x); acc.y = fmaf(v3.y, n3, acc.y);
        acc.z = fmaf(v3.z, n3, acc.z); acc.w = fmaf(v3.w, n3, acc.w);
    }
    for (; e < end; e++) {
        int s0 = __ldg(&g_csr_src[e]);
        float n0 = __ldg(&g_csr_w[e]);
        float4 v0 = h4f(hv[(size_t)s0 * 32 + lane]);
        acc.x = fmaf(v0.x, n0, acc.x); acc.y = fmaf(v0.y, n0, acc.y);
        acc.z = fmaf(v0.z, n0, acc.z); acc.w = fmaf(v0.w, n0, acc.w);
    }
}

#define NPW 8   // nodes per warp; NNODES % 64 == 0 exactly (3125 blocks)

// gather-1: 256 thr = 8 warps = 64 nodes; 1-deep node pipeline (next self-row/dinv
// prefetched before current edge loop); BN sums in registers.
__global__ void gather_split_kernel(const __half* __restrict__ h, uint4* __restrict__ Rq4,
                                    const float* __restrict__ bias, float* __restrict__ sums)
{
    __shared__ float ss[256];
    int tid = threadIdx.x;
    ss[tid] = 0.0f;
    __syncthreads();

    int lane = tid & 31;
    int base = blockIdx.x * 64 + (tid >> 5) * NPW;
    int d = lane * 4;
    float4 b4 = make_float4(bias[d], bias[d + 1], bias[d + 2], bias[d + 3]);
    const uint2* hv = (const uint2*)h;

    float s0 = 0, s1 = 0, s2 = 0, s3 = 0, q0 = 0, q1 = 0, q2 = 0, q3 = 0;

    int   beg   = __ldg(&g_csr_ptr[base]);
    float di    = __ldg(&g_dinv[base]);
    uint2 selfr = hv[(size_t)base * 32 + lane];

#pragma unroll
    for (int i = 0; i < NPW; i++) {
        int node = base + i;
        int end = __ldg(&g_csr_ptr[node + 1]);
        float ndi = 0.0f; uint2 nself = make_uint2(0u, 0u);
        if (i + 1 < NPW) {                       // prefetch next node header
            ndi   = __ldg(&g_dinv[node + 1]);
            nself = hv[(size_t)(node + 1) * 32 + lane];
        }
        float4 acc = h4f(selfr);
        float sn = di * di;
        acc.x *= sn; acc.y *= sn; acc.z *= sn; acc.w *= sn;
        gather_edges(hv, beg, end, lane, acc);

        float v0 = fmaxf(acc.x + b4.x, 0.0f);
        float v1 = fmaxf(acc.y + b4.y, 0.0f);
        float v2 = fmaxf(acc.z + b4.z, 0.0f);
        float v3 = fmaxf(acc.w + b4.w, 0.0f);
        uint32_t h01, l01, h23, l23;
        splitpack(v0, v1, h01, l01);
        splitpack(v2, v3, h23, l23);
        Rq4[(size_t)node * 32 + lane] = make_uint4(h01, l01, h23, l23);
        s0 += v0; q0 += v0 * v0;
        s1 += v1; q1 += v1 * v1;
        s2 += v2; q2 += v2 * v2;
        s3 += v3; q3 += v3 * v3;

        beg = end; di = ndi; selfr = nself;
    }
    atomicAdd(&ss[d + 0], s0);  atomicAdd(&ss[128 + d + 0], q0);
    atomicAdd(&ss[d + 1], s1);  atomicAdd(&ss[128 + d + 1], q1);
    atomicAdd(&ss[d + 2], s2);  atomicAdd(&ss[128 + d + 2], q2);
    atomicAdd(&ss[d + 3], s3);  atomicAdd(&ss[128 + d + 3], q3);
    __syncthreads();
    atomicAdd(&sums[tid], ss[tid]);
}

// gather-2: same pipeline + register pool-max flushed on graph transitions
__global__ void gather_pool_kernel(const __half* __restrict__ h, const int* __restrict__ ibatch,
                                   const float* __restrict__ bias, float* __restrict__ sums)
{
    __shared__ float ss[256];
    int tid = threadIdx.x;
    ss[tid] = 0.0f;
    __syncthreads();

    int lane = tid & 31;
    int base = blockIdx.x * 64 + (tid >> 5) * NPW;
    int d = lane * 4;
    float4 b4 = make_float4(bias[d], bias[d + 1], bias[d + 2], bias[d + 3]);
    const uint2* hv = (const uint2*)h;

    float s0 = 0, s1 = 0, s2 = 0, s3 = 0, q0 = 0, q1 = 0, q2 = 0, q3 = 0;
    float m0 = 0, m1 = 0, m2 = 0, m3 = 0;
    int cur_g = -1;

    int   beg   = __ldg(&g_csr_ptr[base]);
    float di    = __ldg(&g_dinv[base]);
    uint2 selfr = hv[(size_t)base * 32 + lane];

#pragma unroll
    for (int i = 0; i < NPW; i++) {
        int node = base + i;
        int end = __ldg(&g_csr_ptr[node + 1]);
        float ndi = 0.0f; uint2 nself = make_uint2(0u, 0u);
        if (i + 1 < NPW) {
            ndi   = __ldg(&g_dinv[node + 1]);
            nself = hv[(size_t)(node + 1) * 32 + lane];
        }
        int g = 0;
        if (lane == 0) g = __ldg(&ibatch[node]);
        g = __shfl_sync(0xffffffffu, g, 0);
        if (g != cur_g) {
            if (cur_g >= 0) {
                int* mb = g_maxb + cur_g * F + d;
                atomicMax(mb + 0, __float_as_int(m0));
                atomicMax(mb + 1, __float_as_int(m1));
                atomicMax(mb + 2, __float_as_int(m2));
                atomicMax(mb + 3, __float_as_int(m3));
            }
            cur_g = g;
            m0 = m1 = m2 = m3 = 0.0f;
        }
        float4 acc = h4f(selfr);
        float sn = di * di;
        acc.x *= sn; acc.y *= sn; acc.z *= sn; acc.w *= sn;
        gather_edges(hv, beg, end, lane, acc);

        float v0 = fmaxf(acc.x + b4.x, 0.0f);
        float v1 = fmaxf(acc.y + b4.y, 0.0f);
        float v2 = fmaxf(acc.z + b4.z, 0.0f);
        float v3 = fmaxf(acc.w + b4.w, 0.0f);
        m0 = fmaxf(m0, v0); m1 = fmaxf(m1, v1);
        m2 = fmaxf(m2, v2); m3 = fmaxf(m3, v3);
        s0 += v0; q0 += v0 * v0;
        s1 += v1; q1 += v1 * v1;
        s2 += v2; q2 += v2 * v2;
        s3 += v3; q3 += v3 * v3;

        beg = end; di = ndi; selfr = nself;
    }
    if (cur_g >= 0) {
        int* mb = g_maxb + cur_g * F + d;
        atomicMax(mb + 0, __float_as_int(m0));
        atomicMax(mb + 1, __float_as_int(m1));
        atomicMax(mb + 2, __float_as_int(m2));
        atomicMax(mb + 3, __float_as_int(m3));
    }
    atomicAdd(&ss[d + 0], s0);  atomicAdd(&ss[128 + d + 0], q0);
    atomicAdd(&ss[d + 1], s1);  atomicAdd(&ss[128 + d + 1], q1);
    atomicAdd(&ss[d + 2], s2);  atomicAdd(&ss[128 + d + 2], q2);
    atomicAdd(&ss[d + 3], s3);  atomicAdd(&ss[128 + d + 3], q3);
    __syncthreads();
    atomicAdd(&sums[tid], ss[tid]);
}

// out = BN2(max) with affine computed inline from raw sums
__global__ void pool_out_kernel(const float* __restrict__ sums2, const float* __restrict__ g2,
                                const float* __restrict__ be2, float* __restrict__ out)
{
    int idx = blockIdx.x * blockDim.x + threadIdx.x;
    if (idx >= NG * F) return;
    int d = idx & 127;
    const float invM = 1.0f / (float)NNODES;
    float m   = sums2[d] * invM;
    float var = sums2[F + d] * invM - m * m;
    float sc  = g2[d] * rsqrtf(var + BN_EPS);
    float v   = __int_as_float(g_maxb[idx]);
    out[idx]  = fmaf(sc, v, be2[d] - sc * m);
}

// ================= cell branch helpers ==========================================
__global__ void bn_stats_kernel(const float* __restrict__ in, float* __restrict__ sums, int M) {
    int d = threadIdx.x;
    float s = 0.0f, q = 0.0f;
    for (int r = blockIdx.x; r < M; r += gridDim.x) {
        float v = in[(size_t)r * F + d];
        s += v; q += v * v;
    }
    atomicAdd(&sums[d], s);
    atomicAdd(&sums[F + d], q);
}

__global__ void bn_apply_kernel(const float* __restrict__ in, const float* __restrict__ sums,
                                const float* __restrict__ gamma, const float* __restrict__ beta,
                                float* __restrict__ out, int M)
{
    int i = blockIdx.x * blockDim.x + threadIdx.x;
    if (i >= M * F) return;
    int d = i & 127;
    float invM = 1.0f / (float)M;
    float m   = sums[d] * invM;
    float var = sums[F + d] * invM - m * m;
    out[i] = gamma[d] * (in[i] - m) * rsqrtf(var + BN_EPS) + beta[d];
}

__global__ __launch_bounds__(256) void gemm128(
    const float* __restrict__ A, const float* __restrict__ B,
    const float* __restrict__ bias, float* __restrict__ C,
    int M, int K, int act)
{
    __shared__ float As[16][132];
    __shared__ float Bs[16][128];
    const int tid = threadIdx.x;
    const int m0  = blockIdx.x * 128;
    const int tn  = tid & 15;
    const int tm  = tid >> 4;
    float acc[8][8];
#pragma unroll
    for (int i = 0; i < 8; i++)
#pragma unroll
        for (int j = 0; j < 8; j++) acc[i][j] = 0.0f;
    const int arow = tid >> 4, acol = tid & 15;
    const int brow = tid >> 7, bcol = tid & 127;
    for (int kk = 0; kk < K; kk += 16) {
#pragma unroll
        for (int p = 0; p < 8; p++) {
            int m = p * 16 + arow, gk = kk + acol, gm = m0 + m;
            float v = 0.0f;
            if (gm < M && gk < K) v = A[(size_t)gm * K + gk];
            As[acol][m] = v;
        }
#pragma unroll
        for (int q = 0; q < 8; q++) {
            int k = q * 2 + brow, gk = kk + k;
            Bs[k][bcol] = (gk < K) ? B[(size_t)gk * 128 + bcol] : 0.0f;
        }
        __syncthreads();
#pragma unroll
        for (int k = 0; k < 16; k++) {
            float4 a0 = *(const float4*)&As[k][tm * 8];
            float4 a1 = *(const float4*)&As[k][tm * 8 + 4];
            float4 b0 = *(const float4*)&Bs[k][tn * 8];
            float4 b1 = *(const float4*)&Bs[k][tn * 8 + 4];
            float a[8] = {a0.x, a0.y, a0.z, a0.w, a1.x, a1.y, a1.z, a1.w};
            float b[8] = {b0.x, b0.y, b0.z, b0.w, b1.x, b1.y, b1.z, b1.w};
#pragma unroll
            for (int i = 0; i < 8; i++)
#pragma unroll
                for (int j = 0; j < 8; j++)
                    acc[i][j] = fmaf(a[i], b[j], acc[i][j]);
        }
        __syncthreads();
    }
#pragma unroll
    for (int i = 0; i < 8; i++) {
        int gm = m0 + tm * 8 + i;
        if (gm >= M) continue;
        float o[8];
#pragma unroll
        for (int j = 0; j < 8; j++) {
            float v = acc[i][j] + bias[tn * 8 + j];
            if (act == 1)      v = fmaxf(v, 0.0f);
            else if (act == 2) v = tanhf(v);
            o[j] = v;
        }
        float4* cp = (float4*)&C[(size_t)gm * 128 + tn * 8];
        cp[0] = make_float4(o[0], o[1], o[2], o[3]);
        cp[1] = make_float4(o[4], o[5], o[6], o[7]);
    }
}

// ================= launch ========================================================
extern "C" void kernel_launch(void* const* d_in, const int* in_sizes, int n_in,
                              void* d_out, int out_size)
{
    const float* x      = (const float*)d_in[0];
    const int*   eidx   = (const int*)  d_in[1];
    const int*   ibatch = (const int*)  d_in[2];
    const float* gexpr  = (const float*)d_in[3];
    const float* W1  = (const float*)d_in[4];
    const float* b1  = (const float*)d_in[5];
    const float* g1  = (const float*)d_in[6];
    const float* be1 = (const float*)d_in[7];
    const float* W2  = (const float*)d_in[8];
    const float* b2  = (const float*)d_in[9];
    const float* g2  = (const float*)d_in[10];
    const float* be2 = (const float*)d_in[11];
    const float* Wc1 = (const float*)d_in[12];
    const float* bc1 = (const float*)d_in[13];
    const float* gc  = (const float*)d_in[14];
    const float* bec = (const float*)d_in[15];
    const float* Wc2 = (const float*)d_in[16];
    const float* bc2 = (const float*)d_in[17];
    float* out = (float*)d_out;

    const int* src = eidx;
    const int* dst = eidx + NEDGES;

    float* bufA; cudaGetSymbolAddress((void**)&bufA, g_bufA);
    float* bufB; cudaGetSymbolAddress((void**)&bufB, g_bufB);
    float* cell; cudaGetSymbolAddress((void**)&cell, g_cell);
    float* sums; cudaGetSymbolAddress((void**)&sums, g_sums);
    float* cst;  cudaGetSymbolAddress((void**)&cst,  g_const);
    __nv_bfloat16 *w1hi, *w1lo, *w2hi, *w2lo;
    cudaGetSymbolAddress((void**)&w1hi, g_w1hi);
    cudaGetSymbolAddress((void**)&w1lo, g_w1lo);
    cudaGetSymbolAddress((void**)&w2hi, g_w2hi);
    cudaGetSymbolAddress((void**)&w2lo, g_w2lo);
    __half* hbuf = (__half*)bufA;

    cudaFuncSetAttribute(gemm_mma,  cudaFuncAttributeMaxDynamicSharedMemorySize, MMA_SMEM);
    cudaFuncSetAttribute(gemm_lite, cudaFuncAttributeMaxDynamicSharedMemorySize, LITE_SMEM);

    static cudaStream_t s_csr = nullptr, s_cell = nullptr;
    static cudaEvent_t ev_root = nullptr, ev_csr = nullptr, ev_cell = nullptr;
    if (!s_csr) {
        cudaStreamCreateWithFlags(&s_csr,  cudaStreamNonBlocking);
        cudaStreamCreateWithFlags(&s_cell, cudaStreamNonBlocking);
        cudaEventCreateWithFlags(&ev_root, cudaEventDisableTiming);
        cudaEventCreateWithFlags(&ev_csr,  cudaEventDisableTiming);
        cudaEventCreateWithFlags(&ev_cell, cudaEventDisableTiming);
    }

    const int T = 256;
    int gN  = (NNODES + T - 1) / T;
    int gE  = (NEDGES + T - 1) / T;
    int gGF = (NG * F + T - 1) / T;
    int gGather = NNODES / 64;            // 3125 blocks x 8 warps x 8 nodes (exact)
    int gTile   = (NNODES + 127) / 128;   // 1563
    int gGemmG  = (NG + 127) / 128;

    // ---- fork
    cudaEventRecord(ev_root, 0);
    cudaStreamWaitEvent(s_csr,  ev_root, 0);
    cudaStreamWaitEvent(s_cell, ev_root, 0);

    // submissions 1-4 (gemm_mma stays in ncu slot)
    init_kernel<<<gN, T, 0, s_csr>>>();
    deg_kernel<<<gE, T, 0, s_csr>>>(dst);
    wprep1_kernel<<<(F * F + 255) / 256, 256>>>(W1);
    gemm_mma<<<gTile, 256, MMA_SMEM>>>(x, NNODES, w1hi, w1lo, hbuf);

    // ---- rest of CSR branch
    scan1_kernel<<<NBLK, 256, 0, s_csr>>>();
    scan2_kernel<<<1, 1024, 0, s_csr>>>();
    scan3_kernel<<<gN, T, 0, s_csr>>>();
    fill_kernel<<<gE, T, 0, s_csr>>>(src, dst);
    cudaEventRecord(ev_csr, s_csr);

    // ---- cell branch
    zero_cell_sums<<<1, 256, 0, s_cell>>>();
    gemm128<<<gGemmG, 256, 0, s_cell>>>(gexpr, Wc1, bc1, cell, NG, DCELL, 2);
    bn_stats_kernel<<<512, 128, 0, s_cell>>>(cell, sums + 512, NG);
    bn_apply_kernel<<<gGF, T, 0, s_cell>>>(cell, sums + 512, gc, bec, cell, NG);
    gemm128<<<gGemmG, 256, 0, s_cell>>>(cell, Wc2, bc2, out + (size_t)NG * F, NG, 128, 1);
    cudaEventRecord(ev_cell, s_cell);

    // ---- main: join CSR, aggregation pipeline
    cudaStreamWaitEvent(0, ev_csr, 0);
    gather_split_kernel<<<gGather, 256>>>(hbuf, (uint4*)bufB, b1, sums + 0);
    wprep2_kernel<<<128, 128>>>(W2, sums + 0, g1, be1);

    gemm_lite<<<gTile, 256, LITE_SMEM>>>((const uint2*)bufB, NNODES, w2hi, w2lo, cst, hbuf);
    gather_pool_kernel<<<gGather, 256>>>(hbuf, ibatch, b2, sums + 256);
    pool_out_kernel<<<gGF, T>>>(sums + 256, g2, be2, out);

    // ---- join cell branch
    cudaStreamWaitEvent(0, ev_cell, 0);
}